// round 14
// baseline (speedup 1.0000x reference)
#include <cuda_runtime.h>
#include <cuda_bf16.h>
#include <math.h>
#include <stdint.h>

// ---------------- problem constants ----------------
#define BATCH 32
#define HDIM  56
#define WDIM  56
#define CDIM  128
#define NHEAD 4
#define WS    7
#define SS    3
#define LTOK  (HDIM*WDIM)          // 3136
#define NWIN  (WS*WS)              // 49
#define HD    (CDIM/NHEAD)         // 32
#define MROWS (BATCH*LTOK)         // 100352

#define BM 128
#define BN 128
#define BK 32
#define LDB 40   // smem row stride in bf16 elems (80B) -> conflict-free ldmatrix

typedef __nv_bfloat16 bf16;

// ---------------- scratch (device globals; no allocation) ----------------
__device__ bf16  g_qkv [(size_t)MROWS * 3 * CDIM];
__device__ bf16  g_attn[(size_t)MROWS * CDIM];
__device__ float g_x1  [(size_t)MROWS * CDIM];
__device__ bf16  g_h2  [(size_t)MROWS * CDIM];
__device__ bf16  g_wb  [196608];       // qkv(49152) | proj(16384) | fc1(65536) | fc2(65536)
__device__ float g_bias[4 * 64 * 50];  // padded rel-pos bias [h][t(64)][m(50)]

// ---------------- helpers ----------------
__device__ __forceinline__ void ldsm4(uint32_t* r, const bf16* p) {
    uint32_t addr = (uint32_t)__cvta_generic_to_shared(p);
    asm volatile("ldmatrix.sync.aligned.m8n8.x4.shared.b16 {%0,%1,%2,%3}, [%4];"
        : "=r"(r[0]), "=r"(r[1]), "=r"(r[2]), "=r"(r[3]) : "r"(addr));
}

__device__ __forceinline__ void ldsm4t(uint32_t* r, const bf16* p) {
    uint32_t addr = (uint32_t)__cvta_generic_to_shared(p);
    asm volatile("ldmatrix.sync.aligned.m8n8.x4.trans.shared.b16 {%0,%1,%2,%3}, [%4];"
        : "=r"(r[0]), "=r"(r[1]), "=r"(r[2]), "=r"(r[3]) : "r"(addr));
}

__device__ __forceinline__ void mma_bf16(float* d, const uint32_t* a, const uint32_t* b) {
    asm volatile("mma.sync.aligned.m16n8k16.row.col.f32.bf16.bf16.f32 "
        "{%0,%1,%2,%3}, {%4,%5,%6,%7}, {%8,%9}, {%0,%1,%2,%3};"
        : "+f"(d[0]), "+f"(d[1]), "+f"(d[2]), "+f"(d[3])
        : "r"(a[0]), "r"(a[1]), "r"(a[2]), "r"(a[3]), "r"(b[0]), "r"(b[1]));
}

__device__ __forceinline__ uint32_t pack_bf(float lo, float hi) {
    uint32_t r; asm("cvt.rn.bf16x2.f32 %0, %1, %2;" : "=r"(r) : "f"(hi), "f"(lo)); return r;
}

__device__ __forceinline__ void cp16(uint32_t saddr, const void* g) {
    asm volatile("cp.async.cg.shared.global [%0], [%1], 16;" :: "r"(saddr), "l"(g));
}
__device__ __forceinline__ void cp_commit() { asm volatile("cp.async.commit_group;"); }
__device__ __forceinline__ void cp_wait0()  { asm volatile("cp.async.wait_group 0;"); }

// window-reverse + unshift scatter base for token row m (window layout -> image layout)
__device__ __forceinline__ uint32_t win_scatter(int m) {
    int wi = m / NWIN, t = m % NWIN;
    int bb = wi >> 6, wh = (wi >> 3) & 7, ww = wi & 7;
    int ih = t / WS, jw = t % WS;
    int hr = wh * WS + ih + SS; if (hr >= HDIM) hr -= HDIM;
    int wc = ww * WS + jw + SS; if (wc >= WDIM) wc -= WDIM;
    return ((uint32_t)(bb * HDIM + hr) * WDIM + wc) * CDIM;
}

// ---------------- setup: weight conversion + bias table, one launch ---------------------
__global__ void __launch_bounds__(256) setup_kernel(const float* __restrict__ w0,
                                                    const float* __restrict__ w1,
                                                    const float* __restrict__ w2,
                                                    const float* __restrict__ w3,
                                                    bf16* __restrict__ outw,
                                                    const float* __restrict__ rpb,
                                                    const int* __restrict__ rel_idx,
                                                    float* __restrict__ biasb) {
    int t = blockIdx.x * 256 + threadIdx.x;
    if (t < 49152) {
        int i = t * 4;
        const float* src; int j = i;
        if (i < 49152)       { src = w0; }
        else if (i < 65536)  { src = w1; j = i - 49152; }
        else if (i < 131072) { src = w2; j = i - 65536; }
        else                 { src = w3; j = i - 131072; }
        float4 v = *(const float4*)(src + j);
        outw[i]     = __float2bfloat16(v.x);
        outw[i + 1] = __float2bfloat16(v.y);
        outw[i + 2] = __float2bfloat16(v.z);
        outw[i + 3] = __float2bfloat16(v.w);
    } else {
        int i = t - 49152;   // 0..12799
        if (i < 12800) {
            int h = i / 3200, r = i % 3200, tt = r / 50, m = r % 50;
            float v = 0.f;
            if (tt < NWIN && m < NWIN) v = rpb[rel_idx[tt * NWIN + m] * NHEAD + h];
            biasb[i] = v;
        }
    }
}

// ---------------- fused LN1 + QKV GEMM ---------------------------------------------------
// grid (MROWS/128, 3), 256 threads.
// A = LN1(x[window-gathered rows]) computed in-kernel into resident smem (stride 136);
// B double-buffered cp.async; epilogue: bias -> bf16 qkv.
#define AH_S 136
__global__ void __launch_bounds__(256) qkv_fused(const float* __restrict__ x,
                                                 const float* __restrict__ g1,
                                                 const float* __restrict__ b1n,
                                                 const bf16* __restrict__ Bw,
                                                 const float* __restrict__ bias,
                                                 bf16* __restrict__ C) {
    __shared__ bf16 As[BM * AH_S];
    __shared__ bf16 Bs[2][BN * LDB];

    const int tid  = threadIdx.x;
    const int m0   = blockIdx.x * BM;
    const int n0   = blockIdx.y * BN;
    const int warp = tid >> 5, lane = tid & 31;
    const int wm   = (warp & 1) * 64;
    const int wn   = (warp >> 1) * 32;
    const int lrow = tid >> 1, lcol = (tid & 1) * 16;

    const bf16* Bg = Bw + (size_t)(n0 + lrow) * CDIM + lcol;
    uint32_t bDst[2];
    bDst[0] = (uint32_t)__cvta_generic_to_shared(&Bs[0][lrow * LDB + lcol]);
    bDst[1] = (uint32_t)__cvta_generic_to_shared(&Bs[1][lrow * LDB + lcol]);

    // prologue: B stage 0 (overlaps LN phase)
    cp16(bDst[0], Bg); cp16(bDst[0] + 16, Bg + 8);
    cp_commit();

    // ---- LN phase: warp per row, 16 rows each ----
    float4 gg = *(const float4*)(g1 + lane * 4);
    float4 bb = *(const float4*)(b1n + lane * 4);
    for (int r = warp; r < BM; r += 8) {
        const float* xp = x + win_scatter(m0 + r);
        float4 v = *(const float4*)(xp + lane * 4);
        float mu = v.x + v.y + v.z + v.w;
#pragma unroll
        for (int o = 16; o; o >>= 1) mu += __shfl_xor_sync(0xffffffffu, mu, o);
        mu *= (1.0f / 128.0f);
        float d0 = v.x - mu, d1 = v.y - mu, d2 = v.z - mu, d3 = v.w - mu;
        float var = d0 * d0 + d1 * d1 + d2 * d2 + d3 * d3;
#pragma unroll
        for (int o = 16; o; o >>= 1) var += __shfl_xor_sync(0xffffffffu, var, o);
        float inv = rsqrtf(var * (1.0f / 128.0f) + 1e-5f);
        uint32_t p0 = pack_bf(d0 * inv * gg.x + bb.x, d1 * inv * gg.y + bb.y);
        uint32_t p1 = pack_bf(d2 * inv * gg.z + bb.z, d3 * inv * gg.w + bb.w);
        *(uint2*)&As[r * AH_S + lane * 4] = make_uint2(p0, p1);
    }

    float acc[4][4][4];
#pragma unroll
    for (int i = 0; i < 4; i++)
#pragma unroll
        for (int j = 0; j < 4; j++)
#pragma unroll
            for (int k = 0; k < 4; k++) acc[i][j][k] = 0.f;

    const int lr16 = lane & 15, lh = lane >> 4;
    const int bt   = lane >> 3, brw = lane & 7;

    for (int it = 0; it < 4; it++) {
        const int cur = it & 1;
        cp_wait0();
        __syncthreads();     // B stage ready + (it==0) LN stores visible
        if (it + 1 < 4) {
            const bf16* bn = Bg + (it + 1) * BK;
            cp16(bDst[cur ^ 1], bn); cp16(bDst[cur ^ 1] + 16, bn + 8);
            cp_commit();
        }
#pragma unroll
        for (int kk = 0; kk < BK; kk += 16) {
            uint32_t af[4][4], bfr[4][2];
#pragma unroll
            for (int mt = 0; mt < 4; mt++)
                ldsm4(af[mt], &As[(wm + mt * 16 + lr16) * AH_S + it * 32 + kk + lh * 8]);
#pragma unroll
            for (int ntp = 0; ntp < 2; ntp++) {
                uint32_t tmp[4];
                int rn = wn + ntp * 16 + (bt >> 1) * 8 + brw;
                int ck = kk + (bt & 1) * 8;
                ldsm4(tmp, &Bs[cur][rn * LDB + ck]);
                bfr[ntp * 2][0]     = tmp[0]; bfr[ntp * 2][1]     = tmp[1];
                bfr[ntp * 2 + 1][0] = tmp[2]; bfr[ntp * 2 + 1][1] = tmp[3];
            }
#pragma unroll
            for (int mt = 0; mt < 4; mt++)
#pragma unroll
                for (int nt = 0; nt < 4; nt++)
                    mma_bf16(acc[mt][nt], af[mt], bfr[nt]);
        }
    }

    const int gid = lane >> 2, tg = lane & 3;
#pragma unroll
    for (int mt = 0; mt < 4; mt++) {
        int mlo = m0 + wm + mt * 16 + gid;
        int mhi = mlo + 8;
        size_t base_lo = (size_t)mlo * 384;
        size_t base_hi = (size_t)mhi * 384;
#pragma unroll
        for (int nt = 0; nt < 4; nt++) {
            int n = n0 + wn + nt * 8 + 2 * tg;
            float b0 = bias[n], b1 = bias[n + 1];
            *(__nv_bfloat162*)&C[base_lo + n] = __nv_bfloat162(
                __float2bfloat16(acc[mt][nt][0] + b0), __float2bfloat16(acc[mt][nt][1] + b1));
            *(__nv_bfloat162*)&C[base_hi + n] = __nv_bfloat162(
                __float2bfloat16(acc[mt][nt][2] + b0), __float2bfloat16(acc[mt][nt][3] + b1));
        }
    }
}

// ---------------- bf16 tensor-core GEMM, 2-stage cp.async, ONE barrier/iter -------------
// EPI 3 only: bias + window scatter + residual + fused LN2 -> fp32 x1 AND bf16 h2 (N==128)
template<int EPI>
__global__ void __launch_bounds__(256) bgemm(const bf16* __restrict__ A,
                                             const bf16* __restrict__ Bw,
                                             const float* __restrict__ bias,
                                             const float* __restrict__ res,
                                             void* __restrict__ Cv,
                                             const float* __restrict__ g2,
                                             const float* __restrict__ b2,
                                             bf16* __restrict__ out2,
                                             int M, int N, int K) {
    __shared__ bf16 As[2][BM * LDB];
    __shared__ bf16 Bs[2][BN * LDB];

    const int tid  = threadIdx.x;
    const int m0   = blockIdx.x * BM;
    const int n0   = blockIdx.y * BN;
    const int warp = tid >> 5, lane = tid & 31;
    const int wm   = (warp & 1) * 64;
    const int wn   = (warp >> 1) * 32;

    const int lrow = tid >> 1;
    const int lcol = (tid & 1) * 16;
    const bf16* Ag = A  + (size_t)(m0 + lrow) * K + lcol;
    const bf16* Bg = Bw + (size_t)(n0 + lrow) * K + lcol;

    uint32_t aDst[2], bDst[2];
    aDst[0] = (uint32_t)__cvta_generic_to_shared(&As[0][lrow * LDB + lcol]);
    aDst[1] = (uint32_t)__cvta_generic_to_shared(&As[1][lrow * LDB + lcol]);
    bDst[0] = (uint32_t)__cvta_generic_to_shared(&Bs[0][lrow * LDB + lcol]);
    bDst[1] = (uint32_t)__cvta_generic_to_shared(&Bs[1][lrow * LDB + lcol]);

    float acc[4][4][4];
#pragma unroll
    for (int i = 0; i < 4; i++)
#pragma unroll
        for (int j = 0; j < 4; j++)
#pragma unroll
            for (int k = 0; k < 4; k++) acc[i][j][k] = 0.f;

    const int NIT = K / BK;
    cp16(aDst[0], Ag);          cp16(aDst[0] + 16, Ag + 8);
    cp16(bDst[0], Bg);          cp16(bDst[0] + 16, Bg + 8);
    cp_commit();

    const int lr16 = lane & 15, lh = lane >> 4;
    const int bt   = lane >> 3, brw = lane & 7;

    for (int it = 0; it < NIT; it++) {
        const int cur = it & 1;
        cp_wait0();
        __syncthreads();
        if (it + 1 < NIT) {
            const int nxt = cur ^ 1;
            const bf16* an = Ag + (it + 1) * BK;
            const bf16* bn = Bg + (it + 1) * BK;
            cp16(aDst[nxt], an);      cp16(aDst[nxt] + 16, an + 8);
            cp16(bDst[nxt], bn);      cp16(bDst[nxt] + 16, bn + 8);
            cp_commit();
        }
#pragma unroll
        for (int kk = 0; kk < BK; kk += 16) {
            uint32_t af[4][4], bfr[4][2];
#pragma unroll
            for (int mt = 0; mt < 4; mt++)
                ldsm4(af[mt], &As[cur][(wm + mt * 16 + lr16) * LDB + kk + lh * 8]);
#pragma unroll
            for (int ntp = 0; ntp < 2; ntp++) {
                uint32_t tmp[4];
                int rn = wn + ntp * 16 + (bt >> 1) * 8 + brw;
                int ck = kk + (bt & 1) * 8;
                ldsm4(tmp, &Bs[cur][rn * LDB + ck]);
                bfr[ntp * 2][0]     = tmp[0]; bfr[ntp * 2][1]     = tmp[1];
                bfr[ntp * 2 + 1][0] = tmp[2]; bfr[ntp * 2 + 1][1] = tmp[3];
            }
#pragma unroll
            for (int mt = 0; mt < 4; mt++)
#pragma unroll
                for (int nt = 0; nt < 4; nt++)
                    mma_bf16(acc[mt][nt], af[mt], bfr[nt]);
        }
    }
    __syncthreads();

    const int gid = lane >> 2, tg = lane & 3;

    if (EPI == 3) {
        float* red_s = (float*)&As[0][0];
        float* red_q = red_s + 512;
        float* mu_s  = red_q + 512;
        float* inv_s = mu_s + 128;
        const int wnidx = warp >> 1;
        float* x1 = (float*)Cv;

        uint32_t base_lo[4], base_hi[4];
        float psum[4][2], psq[4][2];
#pragma unroll
        for (int mt = 0; mt < 4; mt++) {
            int mlo = m0 + wm + mt * 16 + gid;
            base_lo[mt] = win_scatter(mlo);
            base_hi[mt] = win_scatter(mlo + 8);
            psum[mt][0] = psum[mt][1] = 0.f;
            psq[mt][0]  = psq[mt][1]  = 0.f;
#pragma unroll
            for (int nt = 0; nt < 4; nt++) {
                int n = wn + nt * 8 + 2 * tg;
                float b0 = bias[n], b1 = bias[n + 1];
                float v0 = acc[mt][nt][0] + b0 + res[base_lo[mt] + n];
                float v1 = acc[mt][nt][1] + b1 + res[base_lo[mt] + n + 1];
                float v2 = acc[mt][nt][2] + b0 + res[base_hi[mt] + n];
                float v3 = acc[mt][nt][3] + b1 + res[base_hi[mt] + n + 1];
                *(float2*)&x1[base_lo[mt] + n] = make_float2(v0, v1);
                *(float2*)&x1[base_hi[mt] + n] = make_float2(v2, v3);
                acc[mt][nt][0] = v0; acc[mt][nt][1] = v1;
                acc[mt][nt][2] = v2; acc[mt][nt][3] = v3;
                psum[mt][0] += v0 + v1;          psum[mt][1] += v2 + v3;
                psq[mt][0]  += v0 * v0 + v1 * v1; psq[mt][1] += v2 * v2 + v3 * v3;
            }
        }
#pragma unroll
        for (int mt = 0; mt < 4; mt++) {
#pragma unroll
            for (int hf = 0; hf < 2; hf++) {
                float s = psum[mt][hf], q = psq[mt][hf];
                s += __shfl_xor_sync(0xffffffffu, s, 1);
                s += __shfl_xor_sync(0xffffffffu, s, 2);
                q += __shfl_xor_sync(0xffffffffu, q, 1);
                q += __shfl_xor_sync(0xffffffffu, q, 2);
                if (tg == 0) {
                    int r = wm + mt * 16 + gid + hf * 8;
                    red_s[wnidx * 128 + r] = s;
                    red_q[wnidx * 128 + r] = q;
                }
            }
        }
        __syncthreads();
        if (tid < 128) {
            float s = red_s[tid] + red_s[128 + tid] + red_s[256 + tid] + red_s[384 + tid];
            float q = red_q[tid] + red_q[128 + tid] + red_q[256 + tid] + red_q[384 + tid];
            float mu = s * (1.0f / 128.0f);
            float var = q * (1.0f / 128.0f) - mu * mu;
            mu_s[tid]  = mu;
            inv_s[tid] = rsqrtf(var + 1e-5f);
        }
        __syncthreads();
#pragma unroll
        for (int mt = 0; mt < 4; mt++) {
            int rlo = wm + mt * 16 + gid, rhi = rlo + 8;
            float mlo_mu = mu_s[rlo], mlo_in = inv_s[rlo];
            float mhi_mu = mu_s[rhi], mhi_in = inv_s[rhi];
#pragma unroll
            for (int nt = 0; nt < 4; nt++) {
                int n = wn + nt * 8 + 2 * tg;
                float g0 = g2[n], g1 = g2[n + 1], bb0 = b2[n], bb1 = b2[n + 1];
                float h0 = (acc[mt][nt][0] - mlo_mu) * mlo_in * g0 + bb0;
                float h1 = (acc[mt][nt][1] - mlo_mu) * mlo_in * g1 + bb1;
                float h2v = (acc[mt][nt][2] - mhi_mu) * mhi_in * g0 + bb0;
                float h3 = (acc[mt][nt][3] - mhi_mu) * mhi_in * g1 + bb1;
                *(__nv_bfloat162*)&out2[base_lo[mt] + n] =
                    __nv_bfloat162(__float2bfloat16(h0), __float2bfloat16(h1));
                *(__nv_bfloat162*)&out2[base_hi[mt] + n] =
                    __nv_bfloat162(__float2bfloat16(h2v), __float2bfloat16(h3));
            }
        }
        return;
    }
}

// ---------------- fused MLP: fc1 + GELU (smem) + fc2 + residual -------------------------
#define SMEM_MLP 104448
__global__ void __launch_bounds__(256) mlp_fused(const bf16* __restrict__ h2,
                                                 const bf16* __restrict__ w1,
                                                 const float* __restrict__ b1,
                                                 const bf16* __restrict__ w2,
                                                 const float* __restrict__ b2f,
                                                 const float* __restrict__ x1,
                                                 float* __restrict__ out) {
    extern __shared__ char sm_[];
    bf16* Ah  = (bf16*)sm_;
    bf16* Hid = (bf16*)(sm_ + 17408);
    bf16* Bst = (bf16*)(sm_ + 83968);

    const int tid  = threadIdx.x;
    const int m0   = blockIdx.x * 64;
    const int warp = tid >> 5, lane = tid & 31;
    const int wm   = (warp & 1) * 32;
    const int wn   = (warp >> 1) * 32;
    const int lr16 = lane & 15, lh = lane >> 4;
    const int bt   = lane >> 3, brw = lane & 7;
    const int gid  = lane >> 2, tg  = lane & 3;
    const int lrow = tid >> 1, lcol = (tid & 1) * 16;

    uint32_t bD[2];
    bD[0] = (uint32_t)__cvta_generic_to_shared(&Bst[lrow * 40 + lcol]);
    bD[1] = (uint32_t)__cvta_generic_to_shared(&Bst[5120 + lrow * 40 + lcol]);

    // A tile (h2, 64x128) -> Ah (stride 136); 16B per cp16, 1024 ops total
    {
        int q = tid;
#pragma unroll
        for (int i = 0; i < 4; i++, q += 256) {
            int r = q >> 4, c = (q & 15) * 8;
            cp16((uint32_t)__cvta_generic_to_shared(&Ah[r * 136 + c]),
                 h2 + (size_t)(m0 + r) * 128 + c);
        }
    }
    {
        const bf16* bp = w1 + (size_t)lrow * 128 + lcol;
        cp16(bD[0], bp); cp16(bD[0] + 16, bp + 8);
    }
    cp_commit();

    int buf = 0;
    // ---------------- fc1 + GELU -> Hid ----------------
    for (int nc = 0; nc < 4; nc++) {
        float acc[2][4][4];
#pragma unroll
        for (int i = 0; i < 2; i++)
#pragma unroll
            for (int j = 0; j < 4; j++)
#pragma unroll
                for (int k = 0; k < 4; k++) acc[i][j][k] = 0.f;

        for (int it = 0; it < 4; it++) {
            cp_wait0();
            __syncthreads();
            int nn = nc, ni = it + 1;
            if (ni == 4) { nn++; ni = 0; }
            if (nn < 4) {
                const bf16* bp = w1 + (size_t)(nn * 128 + lrow) * 128 + ni * 32 + lcol;
                cp16(bD[buf ^ 1], bp); cp16(bD[buf ^ 1] + 16, bp + 8);
                cp_commit();
            }
            const bf16* Bbuf = Bst + buf * 5120;
#pragma unroll
            for (int kk = 0; kk < 32; kk += 16) {
                uint32_t af[2][4], bfr[4][2];
#pragma unroll
                for (int mt = 0; mt < 2; mt++)
                    ldsm4(af[mt], &Ah[(wm + mt * 16 + lr16) * 136 + it * 32 + kk + lh * 8]);
#pragma unroll
                for (int ntp = 0; ntp < 2; ntp++) {
                    uint32_t tmp[4];
                    int rn = wn + ntp * 16 + (bt >> 1) * 8 + brw;
                    ldsm4(tmp, &Bbuf[rn * 40 + kk + (bt & 1) * 8]);
                    bfr[ntp * 2][0]     = tmp[0]; bfr[ntp * 2][1]     = tmp[1];
                    bfr[ntp * 2 + 1][0] = tmp[2]; bfr[ntp * 2 + 1][1] = tmp[3];
                }
#pragma unroll
                for (int mt = 0; mt < 2; mt++)
#pragma unroll
                    for (int nt = 0; nt < 4; nt++)
                        mma_bf16(acc[mt][nt], af[mt], bfr[nt]);
            }
            buf ^= 1;
        }
#pragma unroll
        for (int mt = 0; mt < 2; mt++) {
            int rlo = wm + mt * 16 + gid, rhi = rlo + 8;
#pragma unroll
            for (int nt = 0; nt < 4; nt++) {
                int n = wn + nt * 8 + 2 * tg;
                float bb0 = b1[nc * 128 + n], bb1 = b1[nc * 128 + n + 1];
                float v0 = acc[mt][nt][0] + bb0, v1 = acc[mt][nt][1] + bb1;
                float v2 = acc[mt][nt][2] + bb0, v3 = acc[mt][nt][3] + bb1;
                v0 = 0.5f * v0 * (1.0f + erff(v0 * 0.70710678118654752f));
                v1 = 0.5f * v1 * (1.0f + erff(v1 * 0.70710678118654752f));
                v2 = 0.5f * v2 * (1.0f + erff(v2 * 0.70710678118654752f));
                v3 = 0.5f * v3 * (1.0f + erff(v3 * 0.70710678118654752f));
                *(uint32_t*)&Hid[rlo * 520 + nc * 128 + n] = pack_bf(v0, v1);
                *(uint32_t*)&Hid[rhi * 520 + nc * 128 + n] = pack_bf(v2, v3);
            }
        }
    }
    __syncthreads();

    // ---------------- fc2 + bias + residual -> out ----------------
    {
        const bf16* bp = w2 + (size_t)lrow * 512 + lcol;
        cp16(bD[buf], bp); cp16(bD[buf] + 16, bp + 8);
        cp_commit();
    }
    float acc[2][4][4];
#pragma unroll
    for (int i = 0; i < 2; i++)
#pragma unroll
        for (int j = 0; j < 4; j++)
#pragma unroll
            for (int k = 0; k < 4; k++) acc[i][j][k] = 0.f;

    for (int it = 0; it < 16; it++) {
        cp_wait0();
        __syncthreads();
        if (it + 1 < 16) {
            const bf16* bp = w2 + (size_t)lrow * 512 + (it + 1) * 32 + lcol;
            cp16(bD[buf ^ 1], bp); cp16(bD[buf ^ 1] + 16, bp + 8);
            cp_commit();
        }
        const bf16* Bbuf = Bst + buf * 5120;
#pragma unroll
        for (int kk = 0; kk < 32; kk += 16) {
            uint32_t af[2][4], bfr[4][2];
#pragma unroll
            for (int mt = 0; mt < 2; mt++)
                ldsm4(af[mt], &Hid[(wm + mt * 16 + lr16) * 520 + it * 32 + kk + lh * 8]);
#pragma unroll
            for (int ntp = 0; ntp < 2; ntp++) {
                uint32_t tmp[4];
                int rn = wn + ntp * 16 + (bt >> 1) * 8 + brw;
                ldsm4(tmp, &Bbuf[rn * 40 + kk + (bt & 1) * 8]);
                bfr[ntp * 2][0]     = tmp[0]; bfr[ntp * 2][1]     = tmp[1];
                bfr[ntp * 2 + 1][0] = tmp[2]; bfr[ntp * 2 + 1][1] = tmp[3];
            }
#pragma unroll
            for (int mt = 0; mt < 2; mt++)
#pragma unroll
                for (int nt = 0; nt < 4; nt++)
                    mma_bf16(acc[mt][nt], af[mt], bfr[nt]);
        }
        buf ^= 1;
    }

#pragma unroll
    for (int mt = 0; mt < 2; mt++) {
        int rlo = m0 + wm + mt * 16 + gid, rhi = rlo + 8;
#pragma unroll
        for (int nt = 0; nt < 4; nt++) {
            int n = wn + nt * 8 + 2 * tg;
            float bb0 = b2f[n], bb1 = b2f[n + 1];
            float v0 = acc[mt][nt][0] + bb0 + x1[(size_t)rlo * 128 + n];
            float v1 = acc[mt][nt][1] + bb1 + x1[(size_t)rlo * 128 + n + 1];
            float v2 = acc[mt][nt][2] + bb0 + x1[(size_t)rhi * 128 + n];
            float v3 = acc[mt][nt][3] + bb1 + x1[(size_t)rhi * 128 + n + 1];
            *(float2*)&out[(size_t)rlo * 128 + n] = make_float2(v0, v1);
            *(float2*)&out[(size_t)rhi * 128 + n] = make_float2(v2, v3);
        }
    }
}

// ---------------- tensor-core windowed attention --------------------------------------
#define AT_S 40   // Q/K/V smem row stride (bf16)
__global__ void __launch_bounds__(128) attn_mma(const bf16* __restrict__ qkv,
                                                const float* __restrict__ biasb,
                                                bf16* __restrict__ out) {
    const int wi  = blockIdx.x;
    const int hb  = blockIdx.y;
    const int tid = threadIdx.x;
    const int warp = tid >> 5, lane = tid & 31;
    const int hh   = warp >> 1;
    const int half = warp & 1;
    const int r0   = half * 32;
    const int h    = hb * 2 + hh;

    __shared__ bf16 Qs[2][64 * AT_S];
    __shared__ bf16 Ks[2][64 * AT_S];
    __shared__ bf16 Vs[2][64 * AT_S];

    for (int i = tid; i < 600; i += 128) {
        int lh2 = i / 300, rr = i % 300;
        int row = 49 + rr / 20, d2 = rr % 20;
        ((uint32_t*)&Vs[lh2][row * AT_S])[d2] = 0;
    }

    for (int idx = tid; idx < NWIN * 8; idx += 128) {
        int t  = idx >> 3;
        int c8 = (idx & 7) * 8;
        int lh2 = c8 >> 5;
        int d  = c8 & 31;
        const bf16* base = qkv + (size_t)(wi * NWIN + t) * 384 + hb * 64 + c8;
        *(uint4*)&Qs[lh2][t * AT_S + d] = *(const uint4*)(base);
        *(uint4*)&Ks[lh2][t * AT_S + d] = *(const uint4*)(base + 128);
        *(uint4*)&Vs[lh2][t * AT_S + d] = *(const uint4*)(base + 256);
    }
    __syncthreads();

    const int lr16 = lane & 15, lh = lane >> 4;
    const int bt = lane >> 3, brw = lane & 7;
    const int gid = lane >> 2, tg = lane & 3;

    float S[2][8][4];
#pragma unroll
    for (int i = 0; i < 2; i++)
#pragma unroll
        for (int j = 0; j < 8; j++)
#pragma unroll
            for (int k = 0; k < 4; k++) S[i][j][k] = 0.f;

#pragma unroll
    for (int kk = 0; kk < 32; kk += 16) {
        uint32_t af[2][4], bfr[8][2];
        ldsm4(af[0], &Qs[hh][(r0 + lr16)      * AT_S + kk + lh * 8]);
        ldsm4(af[1], &Qs[hh][(r0 + 16 + lr16) * AT_S + kk + lh * 8]);
#pragma unroll
        for (int ntp = 0; ntp < 4; ntp++) {
            uint32_t tmp[4];
            int rn = ntp * 16 + (bt >> 1) * 8 + brw;
            ldsm4(tmp, &Ks[hh][rn * AT_S + kk + (bt & 1) * 8]);
            bfr[ntp * 2][0]     = tmp[0]; bfr[ntp * 2][1]     = tmp[1];
            bfr[ntp * 2 + 1][0] = tmp[2]; bfr[ntp * 2 + 1][1] = tmp[3];
        }
#pragma unroll
        for (int mt = 0; mt < 2; mt++)
#pragma unroll
            for (int nt = 0; nt < 8; nt++)
                mma_bf16(S[mt][nt], af[mt], bfr[nt]);
    }

    const float scale = 0.17677669529663687f;
#pragma unroll
    for (int mt = 0; mt < 2; mt++) {
        int tlo = r0 + mt * 16 + gid;
        int thi = tlo + 8;
        float mlo = -1e30f, mhi = -1e30f;
#pragma unroll
        for (int nt = 0; nt < 8; nt++) {
            int m = nt * 8 + 2 * tg;
            float2 blo = make_float2(0.f, 0.f), bhi = make_float2(0.f, 0.f);
            if (m < NWIN) {
                blo = *(const float2*)&biasb[(h * 64 + tlo) * 50 + m];
                bhi = *(const float2*)&biasb[(h * 64 + thi) * 50 + m];
            }
            float s0 = S[mt][nt][0] * scale + blo.x;
            float s1 = S[mt][nt][1] * scale + blo.y;
            float s2 = S[mt][nt][2] * scale + bhi.x;
            float s3 = S[mt][nt][3] * scale + bhi.y;
            if (m >= NWIN)     { s0 = -1e30f; s2 = -1e30f; }
            if (m + 1 >= NWIN) { s1 = -1e30f; s3 = -1e30f; }
            S[mt][nt][0] = s0; S[mt][nt][1] = s1; S[mt][nt][2] = s2; S[mt][nt][3] = s3;
            mlo = fmaxf(mlo, fmaxf(s0, s1));
            mhi = fmaxf(mhi, fmaxf(s2, s3));
        }
        mlo = fmaxf(mlo, __shfl_xor_sync(0xffffffffu, mlo, 1));
        mlo = fmaxf(mlo, __shfl_xor_sync(0xffffffffu, mlo, 2));
        mhi = fmaxf(mhi, __shfl_xor_sync(0xffffffffu, mhi, 1));
        mhi = fmaxf(mhi, __shfl_xor_sync(0xffffffffu, mhi, 2));
        float slo = 0.f, shi = 0.f;
#pragma unroll
        for (int nt = 0; nt < 8; nt++) {
            float e0 = __expf(S[mt][nt][0] - mlo);
            float e1 = __expf(S[mt][nt][1] - mlo);
            float e2 = __expf(S[mt][nt][2] - mhi);
            float e3 = __expf(S[mt][nt][3] - mhi);
            S[mt][nt][0] = e0; S[mt][nt][1] = e1; S[mt][nt][2] = e2; S[mt][nt][3] = e3;
            slo += e0 + e1; shi += e2 + e3;
        }
        slo += __shfl_xor_sync(0xffffffffu, slo, 1);
        slo += __shfl_xor_sync(0xffffffffu, slo, 2);
        shi += __shfl_xor_sync(0xffffffffu, shi, 1);
        shi += __shfl_xor_sync(0xffffffffu, shi, 2);
        float ilo = 1.0f / slo, ihi = 1.0f / shi;
#pragma unroll
        for (int nt = 0; nt < 8; nt++) {
            S[mt][nt][0] *= ilo; S[mt][nt][1] *= ilo;
            S[mt][nt][2] *= ihi; S[mt][nt][3] *= ihi;
        }
    }

    uint32_t pa[2][4][4];
#pragma unroll
    for (int mt = 0; mt < 2; mt++)
#pragma unroll
        for (int ks = 0; ks < 4; ks++) {
            pa[mt][ks][0] = pack_bf(S[mt][2 * ks][0],     S[mt][2 * ks][1]);
            pa[mt][ks][1] = pack_bf(S[mt][2 * ks][2],     S[mt][2 * ks][3]);
            pa[mt][ks][2] = pack_bf(S[mt][2 * ks + 1][0], S[mt][2 * ks + 1][1]);
            pa[mt][ks][3] = pack_bf(S[mt][2 * ks + 1][2], S[mt][2 * ks + 1][3]);
        }

    float O[2][4][4];
#pragma unroll
    for (int i = 0; i < 2; i++)
#pragma unroll
        for (int j = 0; j < 4; j++)
#pragma unroll
            for (int k = 0; k < 4; k++) O[i][j][k] = 0.f;

#pragma unroll
    for (int ks = 0; ks < 4; ks++) {
        uint32_t bv[4][2];
#pragma unroll
        for (int np = 0; np < 2; np++) {
            uint32_t tmp[4];
            int row = ks * 16 + (bt & 1) * 8 + brw;
            int col = np * 16 + (bt >> 1) * 8;
            ldsm4t(tmp, &Vs[hh][row * AT_S + col]);
            bv[np * 2][0]     = tmp[0]; bv[np * 2][1]     = tmp[1];
            bv[np * 2 + 1][0] = tmp[2]; bv[np * 2 + 1][1] = tmp[3];
        }
#pragma unroll
        for (int mt = 0; mt < 2; mt++)
#pragma unroll
            for (int nd = 0; nd < 4; nd++)
                mma_bf16(O[mt][nd], pa[mt][ks], bv[nd]);
    }

#pragma unroll
    for (int mt = 0; mt < 2; mt++) {
        int tlo = r0 + mt * 16 + gid;
        int thi = tlo + 8;
#pragma unroll
        for (int nd = 0; nd < 4; nd++) {
            int d = nd * 8 + 2 * tg;
            if (tlo < NWIN)
                *(__nv_bfloat162*)&out[(size_t)(wi * NWIN + tlo) * CDIM + h * HD + d] =
                    __nv_bfloat162(__float2bfloat16(O[mt][nd][0]), __float2bfloat16(O[mt][nd][1]));
            if (thi < NWIN)
                *(__nv_bfloat162*)&out[(size_t)(wi * NWIN + thi) * CDIM + h * HD + d] =
                    __nv_bfloat162(__float2bfloat16(O[mt][nd][2]), __float2bfloat16(O[mt][nd][3]));
        }
    }
}

// ---------------- launch ----------------
extern "C" void kernel_launch(void* const* d_in, const int* in_sizes, int n_in,
                              void* d_out, int out_size) {
    const float* x     = (const float*)d_in[0];
    const float* n1g   = (const float*)d_in[1];
    const float* n1b   = (const float*)d_in[2];
    const float* qkvw  = (const float*)d_in[3];
    const float* qkvb  = (const float*)d_in[4];
    const float* rpb   = (const float*)d_in[5];
    const float* projw = (const float*)d_in[6];
    const float* projb = (const float*)d_in[7];
    const float* n2g   = (const float*)d_in[8];
    const float* n2b   = (const float*)d_in[9];
    const float* fc1w  = (const float*)d_in[10];
    const float* fc1b  = (const float*)d_in[11];
    const float* fc2w  = (const float*)d_in[12];
    const float* fc2b  = (const float*)d_in[13];
    const int*   ridx  = (const int*)  d_in[14];
    float* out = (float*)d_out;

    bf16 *qkv, *attn, *h2, *wb;
    float *x1, *biasb;
    cudaGetSymbolAddress((void**)&qkv,   g_qkv);
    cudaGetSymbolAddress((void**)&attn,  g_attn);
    cudaGetSymbolAddress((void**)&x1,    g_x1);
    cudaGetSymbolAddress((void**)&h2,    g_h2);
    cudaGetSymbolAddress((void**)&wb,    g_wb);
    cudaGetSymbolAddress((void**)&biasb, g_bias);

    bf16* qkvw_b  = wb;
    bf16* projw_b = wb + 49152;
    bf16* fc1w_b  = wb + 65536;
    bf16* fc2w_b  = wb + 131072;

    cudaFuncSetAttribute(mlp_fused, cudaFuncAttributeMaxDynamicSharedMemorySize, SMEM_MLP);

    // 0) weight conversion + bias table (one launch)
    setup_kernel<<<243, 256>>>(qkvw, projw, fc1w, fc2w, wb, rpb, ridx, biasb);

    // 1) fused LN1 + QKV projection -> bf16 qkv
    qkv_fused<<<dim3(MROWS / BM, 3), 256>>>(x, n1g, n1b, qkvw_b, qkvb, qkv);

    // 2) tensor-core windowed attention -> bf16
    attn_mma<<<dim3(BATCH * 64, 2), 128>>>(qkv, biasb, attn);

    // 3) proj + window reverse + unshift + residual -> x1 fp32; fused LN2 -> h2 bf16
    bgemm<3><<<dim3(MROWS / BM, 1), 256>>>(attn, projw_b, projb, x, x1,
                                           n2g, n2b, h2,
                                           MROWS, CDIM, CDIM);

    // 4) fused MLP: fc1 + GELU + fc2 + residual -> out fp32
    mlp_fused<<<MROWS / 64, 256, SMEM_MLP>>>(h2, fc1w_b, fc1b, fc2w_b, fc2b, x1, out);
}

// round 15
// speedup vs baseline: 1.1092x; 1.1092x over previous
#include <cuda_runtime.h>
#include <cuda_bf16.h>
#include <math.h>
#include <stdint.h>

// ---------------- problem constants ----------------
#define BATCH 32
#define HDIM  56
#define WDIM  56
#define CDIM  128
#define NHEAD 4
#define WS    7
#define SS    3
#define LTOK  (HDIM*WDIM)          // 3136
#define NWIN  (WS*WS)              // 49
#define HD    (CDIM/NHEAD)         // 32
#define MROWS (BATCH*LTOK)         // 100352

#define BM 128
#define BN 128
#define BK 32
#define LDB 40   // smem row stride in bf16 elems (80B) -> conflict-free ldmatrix

typedef __nv_bfloat16 bf16;

// ---------------- scratch (device globals; no allocation) ----------------
__device__ bf16  g_qkv [(size_t)MROWS * 3 * CDIM];
__device__ bf16  g_attn[(size_t)MROWS * CDIM];
__device__ float g_x1  [(size_t)MROWS * CDIM];
__device__ bf16  g_h2  [(size_t)MROWS * CDIM];
__device__ bf16  g_wb  [196608];       // qkv(49152) | proj(16384) | fc1(65536) | fc2(65536)
__device__ float g_bias[4 * 64 * 50];  // padded rel-pos bias [h][t(64)][m(50)]

// ---------------- helpers ----------------
__device__ __forceinline__ void ldsm4(uint32_t* r, const bf16* p) {
    uint32_t addr = (uint32_t)__cvta_generic_to_shared(p);
    asm volatile("ldmatrix.sync.aligned.m8n8.x4.shared.b16 {%0,%1,%2,%3}, [%4];"
        : "=r"(r[0]), "=r"(r[1]), "=r"(r[2]), "=r"(r[3]) : "r"(addr));
}

__device__ __forceinline__ void ldsm4t(uint32_t* r, const bf16* p) {
    uint32_t addr = (uint32_t)__cvta_generic_to_shared(p);
    asm volatile("ldmatrix.sync.aligned.m8n8.x4.trans.shared.b16 {%0,%1,%2,%3}, [%4];"
        : "=r"(r[0]), "=r"(r[1]), "=r"(r[2]), "=r"(r[3]) : "r"(addr));
}

__device__ __forceinline__ void mma_bf16(float* d, const uint32_t* a, const uint32_t* b) {
    asm volatile("mma.sync.aligned.m16n8k16.row.col.f32.bf16.bf16.f32 "
        "{%0,%1,%2,%3}, {%4,%5,%6,%7}, {%8,%9}, {%0,%1,%2,%3};"
        : "+f"(d[0]), "+f"(d[1]), "+f"(d[2]), "+f"(d[3])
        : "r"(a[0]), "r"(a[1]), "r"(a[2]), "r"(a[3]), "r"(b[0]), "r"(b[1]));
}

__device__ __forceinline__ uint32_t pack_bf(float lo, float hi) {
    uint32_t r; asm("cvt.rn.bf16x2.f32 %0, %1, %2;" : "=r"(r) : "f"(hi), "f"(lo)); return r;
}

__device__ __forceinline__ void cp16(uint32_t saddr, const void* g) {
    asm volatile("cp.async.cg.shared.global [%0], [%1], 16;" :: "r"(saddr), "l"(g));
}
__device__ __forceinline__ void cp_commit() { asm volatile("cp.async.commit_group;"); }
__device__ __forceinline__ void cp_wait0()  { asm volatile("cp.async.wait_group 0;"); }

// window-reverse + unshift scatter base for token row m (window layout -> image layout)
__device__ __forceinline__ uint32_t win_scatter(int m) {
    int wi = m / NWIN, t = m % NWIN;
    int bb = wi >> 6, wh = (wi >> 3) & 7, ww = wi & 7;
    int ih = t / WS, jw = t % WS;
    int hr = wh * WS + ih + SS; if (hr >= HDIM) hr -= HDIM;
    int wc = ww * WS + jw + SS; if (wc >= WDIM) wc -= WDIM;
    return ((uint32_t)(bb * HDIM + hr) * WDIM + wc) * CDIM;
}

// ---------------- setup: weight conversion + bias table, one launch ---------------------
__global__ void __launch_bounds__(256) setup_kernel(const float* __restrict__ w0,
                                                    const float* __restrict__ w1,
                                                    const float* __restrict__ w2,
                                                    const float* __restrict__ w3,
                                                    bf16* __restrict__ outw,
                                                    const float* __restrict__ rpb,
                                                    const int* __restrict__ rel_idx,
                                                    float* __restrict__ biasb) {
    int t = blockIdx.x * 256 + threadIdx.x;
    if (t < 49152) {
        int i = t * 4;
        const float* src; int j = i;
        if (i < 49152)       { src = w0; }
        else if (i < 65536)  { src = w1; j = i - 49152; }
        else if (i < 131072) { src = w2; j = i - 65536; }
        else                 { src = w3; j = i - 131072; }
        float4 v = *(const float4*)(src + j);
        outw[i]     = __float2bfloat16(v.x);
        outw[i + 1] = __float2bfloat16(v.y);
        outw[i + 2] = __float2bfloat16(v.z);
        outw[i + 3] = __float2bfloat16(v.w);
    } else {
        int i = t - 49152;   // 0..12799
        if (i < 12800) {
            int h = i / 3200, r = i % 3200, tt = r / 50, m = r % 50;
            float v = 0.f;
            if (tt < NWIN && m < NWIN) v = rpb[rel_idx[tt * NWIN + m] * NHEAD + h];
            biasb[i] = v;
        }
    }
}

// ---------------- fused LN1 + QKV GEMM (grid.y = 1, N-loop inside) ----------------------
// One block per 128-row tile. LN1 computes A once into resident smem; loop over 3 N-chunks
// of 128 with B double-buffered (single-barrier pattern). Epilogue per chunk overlaps the
// next chunk's B prefetch.
#define AH_S 136
__global__ void __launch_bounds__(256) qkv_fused(const float* __restrict__ x,
                                                 const float* __restrict__ g1,
                                                 const float* __restrict__ b1n,
                                                 const bf16* __restrict__ Bw,
                                                 const float* __restrict__ bias,
                                                 bf16* __restrict__ C) {
    __shared__ bf16 As[BM * AH_S];
    __shared__ bf16 Bs[2][BN * LDB];

    const int tid  = threadIdx.x;
    const int m0   = blockIdx.x * BM;
    const int warp = tid >> 5, lane = tid & 31;
    const int wm   = (warp & 1) * 64;
    const int wn   = (warp >> 1) * 32;
    const int lrow = tid >> 1, lcol = (tid & 1) * 16;

    uint32_t bDst[2];
    bDst[0] = (uint32_t)__cvta_generic_to_shared(&Bs[0][lrow * LDB + lcol]);
    bDst[1] = (uint32_t)__cvta_generic_to_shared(&Bs[1][lrow * LDB + lcol]);

    // prologue: B chunk 0, k-step 0 (overlaps LN phase)
    {
        const bf16* bp = Bw + (size_t)lrow * CDIM + lcol;
        cp16(bDst[0], bp); cp16(bDst[0] + 16, bp + 8);
        cp_commit();
    }

    // ---- LN phase: warp per row, 16 rows each, once per block ----
    float4 gg = *(const float4*)(g1 + lane * 4);
    float4 bb = *(const float4*)(b1n + lane * 4);
    for (int r = warp; r < BM; r += 8) {
        const float* xp = x + win_scatter(m0 + r);
        float4 v = *(const float4*)(xp + lane * 4);
        float mu = v.x + v.y + v.z + v.w;
#pragma unroll
        for (int o = 16; o; o >>= 1) mu += __shfl_xor_sync(0xffffffffu, mu, o);
        mu *= (1.0f / 128.0f);
        float d0 = v.x - mu, d1 = v.y - mu, d2 = v.z - mu, d3 = v.w - mu;
        float var = d0 * d0 + d1 * d1 + d2 * d2 + d3 * d3;
#pragma unroll
        for (int o = 16; o; o >>= 1) var += __shfl_xor_sync(0xffffffffu, var, o);
        float inv = rsqrtf(var * (1.0f / 128.0f) + 1e-5f);
        uint32_t p0 = pack_bf(d0 * inv * gg.x + bb.x, d1 * inv * gg.y + bb.y);
        uint32_t p1 = pack_bf(d2 * inv * gg.z + bb.z, d3 * inv * gg.w + bb.w);
        *(uint2*)&As[r * AH_S + lane * 4] = make_uint2(p0, p1);
    }

    const int lr16 = lane & 15, lh = lane >> 4;
    const int bt   = lane >> 3, brw = lane & 7;
    const int gid  = lane >> 2, tg  = lane & 3;

    float acc[4][4][4];
#pragma unroll
    for (int i = 0; i < 4; i++)
#pragma unroll
        for (int j = 0; j < 4; j++)
#pragma unroll
            for (int k = 0; k < 4; k++) acc[i][j][k] = 0.f;

    for (int it2 = 0; it2 < 12; it2++) {
        const int chunk = it2 >> 2, kstep = it2 & 3;
        const int cur = it2 & 1;
        cp_wait0();
        __syncthreads();    // B stage ready; (it2==0) also publishes LN stores
        if (it2 + 1 < 12) {
            const int nc = (it2 + 1) >> 2, nk = (it2 + 1) & 3;
            const bf16* bp = Bw + (size_t)(nc * 128 + lrow) * CDIM + nk * BK + lcol;
            cp16(bDst[cur ^ 1], bp); cp16(bDst[cur ^ 1] + 16, bp + 8);
            cp_commit();
        }
#pragma unroll
        for (int kk = 0; kk < BK; kk += 16) {
            uint32_t af[4][4], bfr[4][2];
#pragma unroll
            for (int mt = 0; mt < 4; mt++)
                ldsm4(af[mt], &As[(wm + mt * 16 + lr16) * AH_S + kstep * 32 + kk + lh * 8]);
#pragma unroll
            for (int ntp = 0; ntp < 2; ntp++) {
                uint32_t tmp[4];
                int rn = wn + ntp * 16 + (bt >> 1) * 8 + brw;
                int ck = kk + (bt & 1) * 8;
                ldsm4(tmp, &Bs[cur][rn * LDB + ck]);
                bfr[ntp * 2][0]     = tmp[0]; bfr[ntp * 2][1]     = tmp[1];
                bfr[ntp * 2 + 1][0] = tmp[2]; bfr[ntp * 2 + 1][1] = tmp[3];
            }
#pragma unroll
            for (int mt = 0; mt < 4; mt++)
#pragma unroll
                for (int nt = 0; nt < 4; nt++)
                    mma_bf16(acc[mt][nt], af[mt], bfr[nt]);
        }
        if (kstep == 3) {
            // epilogue for this N-chunk (registers + global only; overlaps next prefetch)
            const int n0 = chunk * 128;
#pragma unroll
            for (int mt = 0; mt < 4; mt++) {
                int mlo = m0 + wm + mt * 16 + gid;
                size_t base_lo = (size_t)mlo * 384;
                size_t base_hi = (size_t)(mlo + 8) * 384;
#pragma unroll
                for (int nt = 0; nt < 4; nt++) {
                    int n = n0 + wn + nt * 8 + 2 * tg;
                    float b0 = bias[n], b1 = bias[n + 1];
                    *(__nv_bfloat162*)&C[base_lo + n] = __nv_bfloat162(
                        __float2bfloat16(acc[mt][nt][0] + b0),
                        __float2bfloat16(acc[mt][nt][1] + b1));
                    *(__nv_bfloat162*)&C[base_hi + n] = __nv_bfloat162(
                        __float2bfloat16(acc[mt][nt][2] + b0),
                        __float2bfloat16(acc[mt][nt][3] + b1));
                    acc[mt][nt][0] = 0.f; acc[mt][nt][1] = 0.f;
                    acc[mt][nt][2] = 0.f; acc[mt][nt][3] = 0.f;
                }
            }
        }
    }
}

// ---------------- bf16 tensor-core GEMM, 2-stage cp.async, ONE barrier/iter -------------
// EPI 3: bias + window scatter + residual + fused LN2 -> fp32 x1 AND bf16 h2 (N==128)
template<int EPI>
__global__ void __launch_bounds__(256) bgemm(const bf16* __restrict__ A,
                                             const bf16* __restrict__ Bw,
                                             const float* __restrict__ bias,
                                             const float* __restrict__ res,
                                             void* __restrict__ Cv,
                                             const float* __restrict__ g2,
                                             const float* __restrict__ b2,
                                             bf16* __restrict__ out2,
                                             int M, int N, int K) {
    __shared__ bf16 As[2][BM * LDB];
    __shared__ bf16 Bs[2][BN * LDB];

    const int tid  = threadIdx.x;
    const int m0   = blockIdx.x * BM;
    const int n0   = blockIdx.y * BN;
    const int warp = tid >> 5, lane = tid & 31;
    const int wm   = (warp & 1) * 64;
    const int wn   = (warp >> 1) * 32;

    const int lrow = tid >> 1;
    const int lcol = (tid & 1) * 16;
    const bf16* Ag = A  + (size_t)(m0 + lrow) * K + lcol;
    const bf16* Bg = Bw + (size_t)(n0 + lrow) * K + lcol;

    uint32_t aDst[2], bDst[2];
    aDst[0] = (uint32_t)__cvta_generic_to_shared(&As[0][lrow * LDB + lcol]);
    aDst[1] = (uint32_t)__cvta_generic_to_shared(&As[1][lrow * LDB + lcol]);
    bDst[0] = (uint32_t)__cvta_generic_to_shared(&Bs[0][lrow * LDB + lcol]);
    bDst[1] = (uint32_t)__cvta_generic_to_shared(&Bs[1][lrow * LDB + lcol]);

    float acc[4][4][4];
#pragma unroll
    for (int i = 0; i < 4; i++)
#pragma unroll
        for (int j = 0; j < 4; j++)
#pragma unroll
            for (int k = 0; k < 4; k++) acc[i][j][k] = 0.f;

    const int NIT = K / BK;
    cp16(aDst[0], Ag);          cp16(aDst[0] + 16, Ag + 8);
    cp16(bDst[0], Bg);          cp16(bDst[0] + 16, Bg + 8);
    cp_commit();

    const int lr16 = lane & 15, lh = lane >> 4;
    const int bt   = lane >> 3, brw = lane & 7;

    for (int it = 0; it < NIT; it++) {
        const int cur = it & 1;
        cp_wait0();
        __syncthreads();
        if (it + 1 < NIT) {
            const int nxt = cur ^ 1;
            const bf16* an = Ag + (it + 1) * BK;
            const bf16* bn = Bg + (it + 1) * BK;
            cp16(aDst[nxt], an);      cp16(aDst[nxt] + 16, an + 8);
            cp16(bDst[nxt], bn);      cp16(bDst[nxt] + 16, bn + 8);
            cp_commit();
        }
#pragma unroll
        for (int kk = 0; kk < BK; kk += 16) {
            uint32_t af[4][4], bfr[4][2];
#pragma unroll
            for (int mt = 0; mt < 4; mt++)
                ldsm4(af[mt], &As[cur][(wm + mt * 16 + lr16) * LDB + kk + lh * 8]);
#pragma unroll
            for (int ntp = 0; ntp < 2; ntp++) {
                uint32_t tmp[4];
                int rn = wn + ntp * 16 + (bt >> 1) * 8 + brw;
                int ck = kk + (bt & 1) * 8;
                ldsm4(tmp, &Bs[cur][rn * LDB + ck]);
                bfr[ntp * 2][0]     = tmp[0]; bfr[ntp * 2][1]     = tmp[1];
                bfr[ntp * 2 + 1][0] = tmp[2]; bfr[ntp * 2 + 1][1] = tmp[3];
            }
#pragma unroll
            for (int mt = 0; mt < 4; mt++)
#pragma unroll
                for (int nt = 0; nt < 4; nt++)
                    mma_bf16(acc[mt][nt], af[mt], bfr[nt]);
        }
    }
    __syncthreads();

    const int gid = lane >> 2, tg = lane & 3;

    if (EPI == 3) {
        float* red_s = (float*)&As[0][0];
        float* red_q = red_s + 512;
        float* mu_s  = red_q + 512;
        float* inv_s = mu_s + 128;
        const int wnidx = warp >> 1;
        float* x1 = (float*)Cv;

        uint32_t base_lo[4], base_hi[4];
        float psum[4][2], psq[4][2];
#pragma unroll
        for (int mt = 0; mt < 4; mt++) {
            int mlo = m0 + wm + mt * 16 + gid;
            base_lo[mt] = win_scatter(mlo);
            base_hi[mt] = win_scatter(mlo + 8);
            psum[mt][0] = psum[mt][1] = 0.f;
            psq[mt][0]  = psq[mt][1]  = 0.f;
#pragma unroll
            for (int nt = 0; nt < 4; nt++) {
                int n = wn + nt * 8 + 2 * tg;
                float b0 = bias[n], b1 = bias[n + 1];
                float v0 = acc[mt][nt][0] + b0 + res[base_lo[mt] + n];
                float v1 = acc[mt][nt][1] + b1 + res[base_lo[mt] + n + 1];
                float v2 = acc[mt][nt][2] + b0 + res[base_hi[mt] + n];
                float v3 = acc[mt][nt][3] + b1 + res[base_hi[mt] + n + 1];
                *(float2*)&x1[base_lo[mt] + n] = make_float2(v0, v1);
                *(float2*)&x1[base_hi[mt] + n] = make_float2(v2, v3);
                acc[mt][nt][0] = v0; acc[mt][nt][1] = v1;
                acc[mt][nt][2] = v2; acc[mt][nt][3] = v3;
                psum[mt][0] += v0 + v1;          psum[mt][1] += v2 + v3;
                psq[mt][0]  += v0 * v0 + v1 * v1; psq[mt][1] += v2 * v2 + v3 * v3;
            }
        }
#pragma unroll
        for (int mt = 0; mt < 4; mt++) {
#pragma unroll
            for (int hf = 0; hf < 2; hf++) {
                float s = psum[mt][hf], q = psq[mt][hf];
                s += __shfl_xor_sync(0xffffffffu, s, 1);
                s += __shfl_xor_sync(0xffffffffu, s, 2);
                q += __shfl_xor_sync(0xffffffffu, q, 1);
                q += __shfl_xor_sync(0xffffffffu, q, 2);
                if (tg == 0) {
                    int r = wm + mt * 16 + gid + hf * 8;
                    red_s[wnidx * 128 + r] = s;
                    red_q[wnidx * 128 + r] = q;
                }
            }
        }
        __syncthreads();
        if (tid < 128) {
            float s = red_s[tid] + red_s[128 + tid] + red_s[256 + tid] + red_s[384 + tid];
            float q = red_q[tid] + red_q[128 + tid] + red_q[256 + tid] + red_q[384 + tid];
            float mu = s * (1.0f / 128.0f);
            float var = q * (1.0f / 128.0f) - mu * mu;
            mu_s[tid]  = mu;
            inv_s[tid] = rsqrtf(var + 1e-5f);
        }
        __syncthreads();
#pragma unroll
        for (int mt = 0; mt < 4; mt++) {
            int rlo = wm + mt * 16 + gid, rhi = rlo + 8;
            float mlo_mu = mu_s[rlo], mlo_in = inv_s[rlo];
            float mhi_mu = mu_s[rhi], mhi_in = inv_s[rhi];
#pragma unroll
            for (int nt = 0; nt < 4; nt++) {
                int n = wn + nt * 8 + 2 * tg;
                float g0 = g2[n], g1 = g2[n + 1], bb0 = b2[n], bb1 = b2[n + 1];
                float h0 = (acc[mt][nt][0] - mlo_mu) * mlo_in * g0 + bb0;
                float h1 = (acc[mt][nt][1] - mlo_mu) * mlo_in * g1 + bb1;
                float h2v = (acc[mt][nt][2] - mhi_mu) * mhi_in * g0 + bb0;
                float h3 = (acc[mt][nt][3] - mhi_mu) * mhi_in * g1 + bb1;
                *(__nv_bfloat162*)&out2[base_lo[mt] + n] =
                    __nv_bfloat162(__float2bfloat16(h0), __float2bfloat16(h1));
                *(__nv_bfloat162*)&out2[base_hi[mt] + n] =
                    __nv_bfloat162(__float2bfloat16(h2v), __float2bfloat16(h3));
            }
        }
        return;
    }
}

// ---------------- fused MLP: fc1 + GELU (smem) + fc2 + residual -------------------------
#define SMEM_MLP 104448
__global__ void __launch_bounds__(256) mlp_fused(const bf16* __restrict__ h2,
                                                 const bf16* __restrict__ w1,
                                                 const float* __restrict__ b1,
                                                 const bf16* __restrict__ w2,
                                                 const float* __restrict__ b2f,
                                                 const float* __restrict__ x1,
                                                 float* __restrict__ out) {
    extern __shared__ char sm_[];
    bf16* Ah  = (bf16*)sm_;
    bf16* Hid = (bf16*)(sm_ + 17408);
    bf16* Bst = (bf16*)(sm_ + 83968);

    const int tid  = threadIdx.x;
    const int m0   = blockIdx.x * 64;
    const int warp = tid >> 5, lane = tid & 31;
    const int wm   = (warp & 1) * 32;
    const int wn   = (warp >> 1) * 32;
    const int lr16 = lane & 15, lh = lane >> 4;
    const int bt   = lane >> 3, brw = lane & 7;
    const int gid  = lane >> 2, tg  = lane & 3;
    const int lrow = tid >> 1, lcol = (tid & 1) * 16;

    uint32_t bD[2];
    bD[0] = (uint32_t)__cvta_generic_to_shared(&Bst[lrow * 40 + lcol]);
    bD[1] = (uint32_t)__cvta_generic_to_shared(&Bst[5120 + lrow * 40 + lcol]);

    {
        int q = tid;
#pragma unroll
        for (int i = 0; i < 4; i++, q += 256) {
            int r = q >> 4, c = (q & 15) * 8;
            cp16((uint32_t)__cvta_generic_to_shared(&Ah[r * 136 + c]),
                 h2 + (size_t)(m0 + r) * 128 + c);
        }
    }
    {
        const bf16* bp = w1 + (size_t)lrow * 128 + lcol;
        cp16(bD[0], bp); cp16(bD[0] + 16, bp + 8);
    }
    cp_commit();

    int buf = 0;
    for (int nc = 0; nc < 4; nc++) {
        float acc[2][4][4];
#pragma unroll
        for (int i = 0; i < 2; i++)
#pragma unroll
            for (int j = 0; j < 4; j++)
#pragma unroll
                for (int k = 0; k < 4; k++) acc[i][j][k] = 0.f;

        for (int it = 0; it < 4; it++) {
            cp_wait0();
            __syncthreads();
            int nn = nc, ni = it + 1;
            if (ni == 4) { nn++; ni = 0; }
            if (nn < 4) {
                const bf16* bp = w1 + (size_t)(nn * 128 + lrow) * 128 + ni * 32 + lcol;
                cp16(bD[buf ^ 1], bp); cp16(bD[buf ^ 1] + 16, bp + 8);
                cp_commit();
            }
            const bf16* Bbuf = Bst + buf * 5120;
#pragma unroll
            for (int kk = 0; kk < 32; kk += 16) {
                uint32_t af[2][4], bfr[4][2];
#pragma unroll
                for (int mt = 0; mt < 2; mt++)
                    ldsm4(af[mt], &Ah[(wm + mt * 16 + lr16) * 136 + it * 32 + kk + lh * 8]);
#pragma unroll
                for (int ntp = 0; ntp < 2; ntp++) {
                    uint32_t tmp[4];
                    int rn = wn + ntp * 16 + (bt >> 1) * 8 + brw;
                    ldsm4(tmp, &Bbuf[rn * 40 + kk + (bt & 1) * 8]);
                    bfr[ntp * 2][0]     = tmp[0]; bfr[ntp * 2][1]     = tmp[1];
                    bfr[ntp * 2 + 1][0] = tmp[2]; bfr[ntp * 2 + 1][1] = tmp[3];
                }
#pragma unroll
                for (int mt = 0; mt < 2; mt++)
#pragma unroll
                    for (int nt = 0; nt < 4; nt++)
                        mma_bf16(acc[mt][nt], af[mt], bfr[nt]);
            }
            buf ^= 1;
        }
#pragma unroll
        for (int mt = 0; mt < 2; mt++) {
            int rlo = wm + mt * 16 + gid, rhi = rlo + 8;
#pragma unroll
            for (int nt = 0; nt < 4; nt++) {
                int n = wn + nt * 8 + 2 * tg;
                float bb0 = b1[nc * 128 + n], bb1 = b1[nc * 128 + n + 1];
                float v0 = acc[mt][nt][0] + bb0, v1 = acc[mt][nt][1] + bb1;
                float v2 = acc[mt][nt][2] + bb0, v3 = acc[mt][nt][3] + bb1;
                v0 = 0.5f * v0 * (1.0f + erff(v0 * 0.70710678118654752f));
                v1 = 0.5f * v1 * (1.0f + erff(v1 * 0.70710678118654752f));
                v2 = 0.5f * v2 * (1.0f + erff(v2 * 0.70710678118654752f));
                v3 = 0.5f * v3 * (1.0f + erff(v3 * 0.70710678118654752f));
                *(uint32_t*)&Hid[rlo * 520 + nc * 128 + n] = pack_bf(v0, v1);
                *(uint32_t*)&Hid[rhi * 520 + nc * 128 + n] = pack_bf(v2, v3);
            }
        }
    }
    __syncthreads();

    {
        const bf16* bp = w2 + (size_t)lrow * 512 + lcol;
        cp16(bD[buf], bp); cp16(bD[buf] + 16, bp + 8);
        cp_commit();
    }
    float acc[2][4][4];
#pragma unroll
    for (int i = 0; i < 2; i++)
#pragma unroll
        for (int j = 0; j < 4; j++)
#pragma unroll
            for (int k = 0; k < 4; k++) acc[i][j][k] = 0.f;

    for (int it = 0; it < 16; it++) {
        cp_wait0();
        __syncthreads();
        if (it + 1 < 16) {
            const bf16* bp = w2 + (size_t)lrow * 512 + (it + 1) * 32 + lcol;
            cp16(bD[buf ^ 1], bp); cp16(bD[buf ^ 1] + 16, bp + 8);
            cp_commit();
        }
        const bf16* Bbuf = Bst + buf * 5120;
#pragma unroll
        for (int kk = 0; kk < 32; kk += 16) {
            uint32_t af[2][4], bfr[4][2];
#pragma unroll
            for (int mt = 0; mt < 2; mt++)
                ldsm4(af[mt], &Hid[(wm + mt * 16 + lr16) * 520 + it * 32 + kk + lh * 8]);
#pragma unroll
            for (int ntp = 0; ntp < 2; ntp++) {
                uint32_t tmp[4];
                int rn = wn + ntp * 16 + (bt >> 1) * 8 + brw;
                ldsm4(tmp, &Bbuf[rn * 40 + kk + (bt & 1) * 8]);
                bfr[ntp * 2][0]     = tmp[0]; bfr[ntp * 2][1]     = tmp[1];
                bfr[ntp * 2 + 1][0] = tmp[2]; bfr[ntp * 2 + 1][1] = tmp[3];
            }
#pragma unroll
            for (int mt = 0; mt < 2; mt++)
#pragma unroll
                for (int nt = 0; nt < 4; nt++)
                    mma_bf16(acc[mt][nt], af[mt], bfr[nt]);
        }
        buf ^= 1;
    }

#pragma unroll
    for (int mt = 0; mt < 2; mt++) {
        int rlo = m0 + wm + mt * 16 + gid, rhi = rlo + 8;
#pragma unroll
        for (int nt = 0; nt < 4; nt++) {
            int n = wn + nt * 8 + 2 * tg;
            float bb0 = b2f[n], bb1 = b2f[n + 1];
            float v0 = acc[mt][nt][0] + bb0 + x1[(size_t)rlo * 128 + n];
            float v1 = acc[mt][nt][1] + bb1 + x1[(size_t)rlo * 128 + n + 1];
            float v2 = acc[mt][nt][2] + bb0 + x1[(size_t)rhi * 128 + n];
            float v3 = acc[mt][nt][3] + bb1 + x1[(size_t)rhi * 128 + n + 1];
            *(float2*)&out[(size_t)rlo * 128 + n] = make_float2(v0, v1);
            *(float2*)&out[(size_t)rhi * 128 + n] = make_float2(v2, v3);
        }
    }
}

// ---------------- tensor-core windowed attention --------------------------------------
#define AT_S 40   // Q/K/V smem row stride (bf16)
__global__ void __launch_bounds__(128) attn_mma(const bf16* __restrict__ qkv,
                                                const float* __restrict__ biasb,
                                                bf16* __restrict__ out) {
    const int wi  = blockIdx.x;
    const int hb  = blockIdx.y;
    const int tid = threadIdx.x;
    const int warp = tid >> 5, lane = tid & 31;
    const int hh   = warp >> 1;
    const int half = warp & 1;
    const int r0   = half * 32;
    const int h    = hb * 2 + hh;

    __shared__ bf16 Qs[2][64 * AT_S];
    __shared__ bf16 Ks[2][64 * AT_S];
    __shared__ bf16 Vs[2][64 * AT_S];

    for (int i = tid; i < 600; i += 128) {
        int lh2 = i / 300, rr = i % 300;
        int row = 49 + rr / 20, d2 = rr % 20;
        ((uint32_t*)&Vs[lh2][row * AT_S])[d2] = 0;
    }

    for (int idx = tid; idx < NWIN * 8; idx += 128) {
        int t  = idx >> 3;
        int c8 = (idx & 7) * 8;
        int lh2 = c8 >> 5;
        int d  = c8 & 31;
        const bf16* base = qkv + (size_t)(wi * NWIN + t) * 384 + hb * 64 + c8;
        *(uint4*)&Qs[lh2][t * AT_S + d] = *(const uint4*)(base);
        *(uint4*)&Ks[lh2][t * AT_S + d] = *(const uint4*)(base + 128);
        *(uint4*)&Vs[lh2][t * AT_S + d] = *(const uint4*)(base + 256);
    }
    __syncthreads();

    const int lr16 = lane & 15, lh = lane >> 4;
    const int bt = lane >> 3, brw = lane & 7;
    const int gid = lane >> 2, tg = lane & 3;

    float S[2][8][4];
#pragma unroll
    for (int i = 0; i < 2; i++)
#pragma unroll
        for (int j = 0; j < 8; j++)
#pragma unroll
            for (int k = 0; k < 4; k++) S[i][j][k] = 0.f;

#pragma unroll
    for (int kk = 0; kk < 32; kk += 16) {
        uint32_t af[2][4], bfr[8][2];
        ldsm4(af[0], &Qs[hh][(r0 + lr16)      * AT_S + kk + lh * 8]);
        ldsm4(af[1], &Qs[hh][(r0 + 16 + lr16) * AT_S + kk + lh * 8]);
#pragma unroll
        for (int ntp = 0; ntp < 4; ntp++) {
            uint32_t tmp[4];
            int rn = ntp * 16 + (bt >> 1) * 8 + brw;
            ldsm4(tmp, &Ks[hh][rn * AT_S + kk + (bt & 1) * 8]);
            bfr[ntp * 2][0]     = tmp[0]; bfr[ntp * 2][1]     = tmp[1];
            bfr[ntp * 2 + 1][0] = tmp[2]; bfr[ntp * 2 + 1][1] = tmp[3];
        }
#pragma unroll
        for (int mt = 0; mt < 2; mt++)
#pragma unroll
            for (int nt = 0; nt < 8; nt++)
                mma_bf16(S[mt][nt], af[mt], bfr[nt]);
    }

    const float scale = 0.17677669529663687f;
#pragma unroll
    for (int mt = 0; mt < 2; mt++) {
        int tlo = r0 + mt * 16 + gid;
        int thi = tlo + 8;
        float mlo = -1e30f, mhi = -1e30f;
#pragma unroll
        for (int nt = 0; nt < 8; nt++) {
            int m = nt * 8 + 2 * tg;
            float2 blo = make_float2(0.f, 0.f), bhi = make_float2(0.f, 0.f);
            if (m < NWIN) {
                blo = *(const float2*)&biasb[(h * 64 + tlo) * 50 + m];
                bhi = *(const float2*)&biasb[(h * 64 + thi) * 50 + m];
            }
            float s0 = S[mt][nt][0] * scale + blo.x;
            float s1 = S[mt][nt][1] * scale + blo.y;
            float s2 = S[mt][nt][2] * scale + bhi.x;
            float s3 = S[mt][nt][3] * scale + bhi.y;
            if (m >= NWIN)     { s0 = -1e30f; s2 = -1e30f; }
            if (m + 1 >= NWIN) { s1 = -1e30f; s3 = -1e30f; }
            S[mt][nt][0] = s0; S[mt][nt][1] = s1; S[mt][nt][2] = s2; S[mt][nt][3] = s3;
            mlo = fmaxf(mlo, fmaxf(s0, s1));
            mhi = fmaxf(mhi, fmaxf(s2, s3));
        }
        mlo = fmaxf(mlo, __shfl_xor_sync(0xffffffffu, mlo, 1));
        mlo = fmaxf(mlo, __shfl_xor_sync(0xffffffffu, mlo, 2));
        mhi = fmaxf(mhi, __shfl_xor_sync(0xffffffffu, mhi, 1));
        mhi = fmaxf(mhi, __shfl_xor_sync(0xffffffffu, mhi, 2));
        float slo = 0.f, shi = 0.f;
#pragma unroll
        for (int nt = 0; nt < 8; nt++) {
            float e0 = __expf(S[mt][nt][0] - mlo);
            float e1 = __expf(S[mt][nt][1] - mlo);
            float e2 = __expf(S[mt][nt][2] - mhi);
            float e3 = __expf(S[mt][nt][3] - mhi);
            S[mt][nt][0] = e0; S[mt][nt][1] = e1; S[mt][nt][2] = e2; S[mt][nt][3] = e3;
            slo += e0 + e1; shi += e2 + e3;
        }
        slo += __shfl_xor_sync(0xffffffffu, slo, 1);
        slo += __shfl_xor_sync(0xffffffffu, slo, 2);
        shi += __shfl_xor_sync(0xffffffffu, shi, 1);
        shi += __shfl_xor_sync(0xffffffffu, shi, 2);
        float ilo = 1.0f / slo, ihi = 1.0f / shi;
#pragma unroll
        for (int nt = 0; nt < 8; nt++) {
            S[mt][nt][0] *= ilo; S[mt][nt][1] *= ilo;
            S[mt][nt][2] *= ihi; S[mt][nt][3] *= ihi;
        }
    }

    uint32_t pa[2][4][4];
#pragma unroll
    for (int mt = 0; mt < 2; mt++)
#pragma unroll
        for (int ks = 0; ks < 4; ks++) {
            pa[mt][ks][0] = pack_bf(S[mt][2 * ks][0],     S[mt][2 * ks][1]);
            pa[mt][ks][1] = pack_bf(S[mt][2 * ks][2],     S[mt][2 * ks][3]);
            pa[mt][ks][2] = pack_bf(S[mt][2 * ks + 1][0], S[mt][2 * ks + 1][1]);
            pa[mt][ks][3] = pack_bf(S[mt][2 * ks + 1][2], S[mt][2 * ks + 1][3]);
        }

    float O[2][4][4];
#pragma unroll
    for (int i = 0; i < 2; i++)
#pragma unroll
        for (int j = 0; j < 4; j++)
#pragma unroll
            for (int k = 0; k < 4; k++) O[i][j][k] = 0.f;

#pragma unroll
    for (int ks = 0; ks < 4; ks++) {
        uint32_t bv[4][2];
#pragma unroll
        for (int np = 0; np < 2; np++) {
            uint32_t tmp[4];
            int row = ks * 16 + (bt & 1) * 8 + brw;
            int col = np * 16 + (bt >> 1) * 8;
            ldsm4t(tmp, &Vs[hh][row * AT_S + col]);
            bv[np * 2][0]     = tmp[0]; bv[np * 2][1]     = tmp[1];
            bv[np * 2 + 1][0] = tmp[2]; bv[np * 2 + 1][1] = tmp[3];
        }
#pragma unroll
        for (int mt = 0; mt < 2; mt++)
#pragma unroll
            for (int nd = 0; nd < 4; nd++)
                mma_bf16(O[mt][nd], pa[mt][ks], bv[nd]);
    }

#pragma unroll
    for (int mt = 0; mt < 2; mt++) {
        int tlo = r0 + mt * 16 + gid;
        int thi = tlo + 8;
#pragma unroll
        for (int nd = 0; nd < 4; nd++) {
            int d = nd * 8 + 2 * tg;
            if (tlo < NWIN)
                *(__nv_bfloat162*)&out[(size_t)(wi * NWIN + tlo) * CDIM + h * HD + d] =
                    __nv_bfloat162(__float2bfloat16(O[mt][nd][0]), __float2bfloat16(O[mt][nd][1]));
            if (thi < NWIN)
                *(__nv_bfloat162*)&out[(size_t)(wi * NWIN + thi) * CDIM + h * HD + d] =
                    __nv_bfloat162(__float2bfloat16(O[mt][nd][2]), __float2bfloat16(O[mt][nd][3]));
        }
    }
}

// ---------------- launch ----------------
extern "C" void kernel_launch(void* const* d_in, const int* in_sizes, int n_in,
                              void* d_out, int out_size) {
    const float* x     = (const float*)d_in[0];
    const float* n1g   = (const float*)d_in[1];
    const float* n1b   = (const float*)d_in[2];
    const float* qkvw  = (const float*)d_in[3];
    const float* qkvb  = (const float*)d_in[4];
    const float* rpb   = (const float*)d_in[5];
    const float* projw = (const float*)d_in[6];
    const float* projb = (const float*)d_in[7];
    const float* n2g   = (const float*)d_in[8];
    const float* n2b   = (const float*)d_in[9];
    const float* fc1w  = (const float*)d_in[10];
    const float* fc1b  = (const float*)d_in[11];
    const float* fc2w  = (const float*)d_in[12];
    const float* fc2b  = (const float*)d_in[13];
    const int*   ridx  = (const int*)  d_in[14];
    float* out = (float*)d_out;

    bf16 *qkv, *attn, *h2, *wb;
    float *x1, *biasb;
    cudaGetSymbolAddress((void**)&qkv,   g_qkv);
    cudaGetSymbolAddress((void**)&attn,  g_attn);
    cudaGetSymbolAddress((void**)&x1,    g_x1);
    cudaGetSymbolAddress((void**)&h2,    g_h2);
    cudaGetSymbolAddress((void**)&wb,    g_wb);
    cudaGetSymbolAddress((void**)&biasb, g_bias);

    bf16* qkvw_b  = wb;
    bf16* projw_b = wb + 49152;
    bf16* fc1w_b  = wb + 65536;
    bf16* fc2w_b  = wb + 131072;

    cudaFuncSetAttribute(mlp_fused, cudaFuncAttributeMaxDynamicSharedMemorySize, SMEM_MLP);

    // 0) weight conversion + bias table (one launch)
    setup_kernel<<<243, 256>>>(qkvw, projw, fc1w, fc2w, wb, rpb, ridx, biasb);

    // 1) fused LN1 + QKV projection (LN once per block, N-loop inside) -> bf16 qkv
    qkv_fused<<<MROWS / BM, 256>>>(x, n1g, n1b, qkvw_b, qkvb, qkv);

    // 2) tensor-core windowed attention -> bf16
    attn_mma<<<dim3(BATCH * 64, 2), 128>>>(qkv, biasb, attn);

    // 3) proj + window reverse + unshift + residual -> x1 fp32; fused LN2 -> h2 bf16
    bgemm<3><<<dim3(MROWS / BM, 1), 256>>>(attn, projw_b, projb, x, x1,
                                           n2g, n2b, h2,
                                           MROWS, CDIM, CDIM);

    // 4) fused MLP: fc1 + GELU + fc2 + residual -> out fp32
    mlp_fused<<<MROWS / 64, 256, SMEM_MLP>>>(h2, fc1w_b, fc1b, fc2w_b, fc2b, x1, out);
}

// round 16
// speedup vs baseline: 1.1612x; 1.0469x over previous
#include <cuda_runtime.h>
#include <cuda_bf16.h>
#include <math.h>
#include <stdint.h>

// ---------------- problem constants ----------------
#define BATCH 32
#define HDIM  56
#define WDIM  56
#define CDIM  128
#define NHEAD 4
#define WS    7
#define SS    3
#define LTOK  (HDIM*WDIM)          // 3136
#define NWIN  (WS*WS)              // 49
#define HD    (CDIM/NHEAD)         // 32
#define MROWS (BATCH*LTOK)         // 100352

#define BM 128
#define BN 128
#define BK 32
#define LDB 40   // smem row stride in bf16 elems (80B) -> conflict-free ldmatrix

typedef __nv_bfloat16 bf16;

// ---------------- scratch (device globals; no allocation) ----------------
__device__ bf16  g_xw  [(size_t)MROWS * CDIM];
__device__ bf16  g_qkv [(size_t)MROWS * 3 * CDIM];
__device__ bf16  g_attn[(size_t)MROWS * CDIM];
__device__ float g_x1  [(size_t)MROWS * CDIM];
__device__ bf16  g_h2  [(size_t)MROWS * CDIM];
__device__ bf16  g_wb  [196608];       // qkv(49152) | proj(16384) | fc1(65536) | fc2(65536)
__device__ float g_bias[4 * 64 * 50];  // padded rel-pos bias [h][t(64)][m(50)]

// ---------------- helpers ----------------
__device__ __forceinline__ void ldsm4(uint32_t* r, const bf16* p) {
    uint32_t addr = (uint32_t)__cvta_generic_to_shared(p);
    asm volatile("ldmatrix.sync.aligned.m8n8.x4.shared.b16 {%0,%1,%2,%3}, [%4];"
        : "=r"(r[0]), "=r"(r[1]), "=r"(r[2]), "=r"(r[3]) : "r"(addr));
}

__device__ __forceinline__ void ldsm4t(uint32_t* r, const bf16* p) {
    uint32_t addr = (uint32_t)__cvta_generic_to_shared(p);
    asm volatile("ldmatrix.sync.aligned.m8n8.x4.trans.shared.b16 {%0,%1,%2,%3}, [%4];"
        : "=r"(r[0]), "=r"(r[1]), "=r"(r[2]), "=r"(r[3]) : "r"(addr));
}

__device__ __forceinline__ void mma_bf16(float* d, const uint32_t* a, const uint32_t* b) {
    asm volatile("mma.sync.aligned.m16n8k16.row.col.f32.bf16.bf16.f32 "
        "{%0,%1,%2,%3}, {%4,%5,%6,%7}, {%8,%9}, {%0,%1,%2,%3};"
        : "+f"(d[0]), "+f"(d[1]), "+f"(d[2]), "+f"(d[3])
        : "r"(a[0]), "r"(a[1]), "r"(a[2]), "r"(a[3]), "r"(b[0]), "r"(b[1]));
}

__device__ __forceinline__ uint32_t pack_bf(float lo, float hi) {
    uint32_t r; asm("cvt.rn.bf16x2.f32 %0, %1, %2;" : "=r"(r) : "f"(hi), "f"(lo)); return r;
}

__device__ __forceinline__ void cp16(uint32_t saddr, const void* g) {
    asm volatile("cp.async.cg.shared.global [%0], [%1], 16;" :: "r"(saddr), "l"(g));
}
__device__ __forceinline__ void cp_commit() { asm volatile("cp.async.commit_group;"); }
__device__ __forceinline__ void cp_wait0()  { asm volatile("cp.async.wait_group 0;"); }

// window-reverse + unshift scatter base for token row m (window layout -> image layout)
__device__ __forceinline__ uint32_t win_scatter(int m) {
    int wi = m / NWIN, t = m % NWIN;
    int bb = wi >> 6, wh = (wi >> 3) & 7, ww = wi & 7;
    int ih = t / WS, jw = t % WS;
    int hr = wh * WS + ih + SS; if (hr >= HDIM) hr -= HDIM;
    int wc = ww * WS + jw + SS; if (wc >= WDIM) wc -= WDIM;
    return ((uint32_t)(bb * HDIM + hr) * WDIM + wc) * CDIM;
}

// ---------------- setup: weight conversion + bias table, one launch ---------------------
__global__ void __launch_bounds__(256) setup_kernel(const float* __restrict__ w0,
                                                    const float* __restrict__ w1,
                                                    const float* __restrict__ w2,
                                                    const float* __restrict__ w3,
                                                    bf16* __restrict__ outw,
                                                    const float* __restrict__ rpb,
                                                    const int* __restrict__ rel_idx,
                                                    float* __restrict__ biasb) {
    int t = blockIdx.x * 256 + threadIdx.x;
    if (t < 49152) {
        int i = t * 4;
        const float* src; int j = i;
        if (i < 49152)       { src = w0; }
        else if (i < 65536)  { src = w1; j = i - 49152; }
        else if (i < 131072) { src = w2; j = i - 65536; }
        else                 { src = w3; j = i - 131072; }
        float4 v = *(const float4*)(src + j);
        outw[i]     = __float2bfloat16(v.x);
        outw[i + 1] = __float2bfloat16(v.y);
        outw[i + 2] = __float2bfloat16(v.z);
        outw[i + 3] = __float2bfloat16(v.w);
    } else {
        int i = t - 49152;   // 0..12799
        if (i < 12800) {
            int h = i / 3200, r = i % 3200, tt = r / 50, m = r % 50;
            float v = 0.f;
            if (tt < NWIN && m < NWIN) v = rpb[rel_idx[tt * NWIN + m] * NHEAD + h];
            biasb[i] = v;
        }
    }
}

// ---------------- LayerNorm (warp per token, vectorized) -> bf16 with window gather -----
__global__ void __launch_bounds__(256) ln_kernel(const float* __restrict__ x,
                                                 const float* __restrict__ g,
                                                 const float* __restrict__ b,
                                                 bf16* __restrict__ out) {
    int gw   = (blockIdx.x * blockDim.x + threadIdx.x) >> 5;
    int lane = threadIdx.x & 31;
    if (gw >= MROWS) return;

    const float* xp = x + win_scatter(gw);
    float4 v  = *(const float4*)(xp + lane * 4);
    float4 gg = *(const float4*)(g + lane * 4);
    float4 bb = *(const float4*)(b + lane * 4);

    float mu = v.x + v.y + v.z + v.w;
#pragma unroll
    for (int o = 16; o; o >>= 1) mu += __shfl_xor_sync(0xffffffffu, mu, o);
    mu *= (1.0f / 128.0f);
    float d0 = v.x - mu, d1 = v.y - mu, d2 = v.z - mu, d3 = v.w - mu;
    float var = d0 * d0 + d1 * d1 + d2 * d2 + d3 * d3;
#pragma unroll
    for (int o = 16; o; o >>= 1) var += __shfl_xor_sync(0xffffffffu, var, o);
    float inv = rsqrtf(var * (1.0f / 128.0f) + 1e-5f);

    uint32_t p0 = pack_bf(d0 * inv * gg.x + bb.x, d1 * inv * gg.y + bb.y);
    uint32_t p1 = pack_bf(d2 * inv * gg.z + bb.z, d3 * inv * gg.w + bb.w);
    *(uint2*)&out[(size_t)gw * CDIM + lane * 4] = make_uint2(p0, p1);
}

// ---------------- bf16 tensor-core GEMM, 2-stage cp.async, ONE barrier/iter -------------
// EPI 0: bias only -> bf16 out
// EPI 3: bias + window scatter + residual + fused LN2 -> fp32 x1 AND bf16 h2 (N==128)
template<int EPI>
__global__ void __launch_bounds__(256) bgemm(const bf16* __restrict__ A,
                                             const bf16* __restrict__ Bw,
                                             const float* __restrict__ bias,
                                             const float* __restrict__ res,
                                             void* __restrict__ Cv,
                                             const float* __restrict__ g2,
                                             const float* __restrict__ b2,
                                             bf16* __restrict__ out2,
                                             int M, int N, int K) {
    __shared__ bf16 As[2][BM * LDB];
    __shared__ bf16 Bs[2][BN * LDB];

    const int tid  = threadIdx.x;
    const int m0   = blockIdx.x * BM;
    const int n0   = blockIdx.y * BN;
    const int warp = tid >> 5, lane = tid & 31;
    const int wm   = (warp & 1) * 64;
    const int wn   = (warp >> 1) * 32;

    const int lrow = tid >> 1;
    const int lcol = (tid & 1) * 16;
    const bf16* Ag = A  + (size_t)(m0 + lrow) * K + lcol;
    const bf16* Bg = Bw + (size_t)(n0 + lrow) * K + lcol;

    uint32_t aDst[2], bDst[2];
    aDst[0] = (uint32_t)__cvta_generic_to_shared(&As[0][lrow * LDB + lcol]);
    aDst[1] = (uint32_t)__cvta_generic_to_shared(&As[1][lrow * LDB + lcol]);
    bDst[0] = (uint32_t)__cvta_generic_to_shared(&Bs[0][lrow * LDB + lcol]);
    bDst[1] = (uint32_t)__cvta_generic_to_shared(&Bs[1][lrow * LDB + lcol]);

    float acc[4][4][4];
#pragma unroll
    for (int i = 0; i < 4; i++)
#pragma unroll
        for (int j = 0; j < 4; j++)
#pragma unroll
            for (int k = 0; k < 4; k++) acc[i][j][k] = 0.f;

    const int NIT = K / BK;
    cp16(aDst[0], Ag);          cp16(aDst[0] + 16, Ag + 8);
    cp16(bDst[0], Bg);          cp16(bDst[0] + 16, Bg + 8);
    cp_commit();

    const int lr16 = lane & 15, lh = lane >> 4;
    const int bt   = lane >> 3, brw = lane & 7;

    for (int it = 0; it < NIT; it++) {
        const int cur = it & 1;
        cp_wait0();
        __syncthreads();
        if (it + 1 < NIT) {
            const int nxt = cur ^ 1;
            const bf16* an = Ag + (it + 1) * BK;
            const bf16* bn = Bg + (it + 1) * BK;
            cp16(aDst[nxt], an);      cp16(aDst[nxt] + 16, an + 8);
            cp16(bDst[nxt], bn);      cp16(bDst[nxt] + 16, bn + 8);
            cp_commit();
        }
#pragma unroll
        for (int kk = 0; kk < BK; kk += 16) {
            uint32_t af[4][4], bfr[4][2];
#pragma unroll
            for (int mt = 0; mt < 4; mt++)
                ldsm4(af[mt], &As[cur][(wm + mt * 16 + lr16) * LDB + kk + lh * 8]);
#pragma unroll
            for (int ntp = 0; ntp < 2; ntp++) {
                uint32_t tmp[4];
                int rn = wn + ntp * 16 + (bt >> 1) * 8 + brw;
                int ck = kk + (bt & 1) * 8;
                ldsm4(tmp, &Bs[cur][rn * LDB + ck]);
                bfr[ntp * 2][0]     = tmp[0]; bfr[ntp * 2][1]     = tmp[1];
                bfr[ntp * 2 + 1][0] = tmp[2]; bfr[ntp * 2 + 1][1] = tmp[3];
            }
#pragma unroll
            for (int mt = 0; mt < 4; mt++)
#pragma unroll
                for (int nt = 0; nt < 4; nt++)
                    mma_bf16(acc[mt][nt], af[mt], bfr[nt]);
        }
    }
    __syncthreads();

    const int gid = lane >> 2, tg = lane & 3;

    if (EPI == 3) {
        float* red_s = (float*)&As[0][0];
        float* red_q = red_s + 512;
        float* mu_s  = red_q + 512;
        float* inv_s = mu_s + 128;
        const int wnidx = warp >> 1;
        float* x1 = (float*)Cv;

        uint32_t base_lo[4], base_hi[4];
        float psum[4][2], psq[4][2];
#pragma unroll
        for (int mt = 0; mt < 4; mt++) {
            int mlo = m0 + wm + mt * 16 + gid;
            base_lo[mt] = win_scatter(mlo);
            base_hi[mt] = win_scatter(mlo + 8);
            psum[mt][0] = psum[mt][1] = 0.f;
            psq[mt][0]  = psq[mt][1]  = 0.f;
#pragma unroll
            for (int nt = 0; nt < 4; nt++) {
                int n = wn + nt * 8 + 2 * tg;
                float b0 = bias[n], b1 = bias[n + 1];
                float v0 = acc[mt][nt][0] + b0 + res[base_lo[mt] + n];
                float v1 = acc[mt][nt][1] + b1 + res[base_lo[mt] + n + 1];
                float v2 = acc[mt][nt][2] + b0 + res[base_hi[mt] + n];
                float v3 = acc[mt][nt][3] + b1 + res[base_hi[mt] + n + 1];
                *(float2*)&x1[base_lo[mt] + n] = make_float2(v0, v1);
                *(float2*)&x1[base_hi[mt] + n] = make_float2(v2, v3);
                acc[mt][nt][0] = v0; acc[mt][nt][1] = v1;
                acc[mt][nt][2] = v2; acc[mt][nt][3] = v3;
                psum[mt][0] += v0 + v1;          psum[mt][1] += v2 + v3;
                psq[mt][0]  += v0 * v0 + v1 * v1; psq[mt][1] += v2 * v2 + v3 * v3;
            }
        }
#pragma unroll
        for (int mt = 0; mt < 4; mt++) {
#pragma unroll
            for (int hf = 0; hf < 2; hf++) {
                float s = psum[mt][hf], q = psq[mt][hf];
                s += __shfl_xor_sync(0xffffffffu, s, 1);
                s += __shfl_xor_sync(0xffffffffu, s, 2);
                q += __shfl_xor_sync(0xffffffffu, q, 1);
                q += __shfl_xor_sync(0xffffffffu, q, 2);
                if (tg == 0) {
                    int r = wm + mt * 16 + gid + hf * 8;
                    red_s[wnidx * 128 + r] = s;
                    red_q[wnidx * 128 + r] = q;
                }
            }
        }
        __syncthreads();
        if (tid < 128) {
            float s = red_s[tid] + red_s[128 + tid] + red_s[256 + tid] + red_s[384 + tid];
            float q = red_q[tid] + red_q[128 + tid] + red_q[256 + tid] + red_q[384 + tid];
            float mu = s * (1.0f / 128.0f);
            float var = q * (1.0f / 128.0f) - mu * mu;
            mu_s[tid]  = mu;
            inv_s[tid] = rsqrtf(var + 1e-5f);
        }
        __syncthreads();
#pragma unroll
        for (int mt = 0; mt < 4; mt++) {
            int rlo = wm + mt * 16 + gid, rhi = rlo + 8;
            float mlo_mu = mu_s[rlo], mlo_in = inv_s[rlo];
            float mhi_mu = mu_s[rhi], mhi_in = inv_s[rhi];
#pragma unroll
            for (int nt = 0; nt < 4; nt++) {
                int n = wn + nt * 8 + 2 * tg;
                float g0 = g2[n], g1 = g2[n + 1], bb0 = b2[n], bb1 = b2[n + 1];
                float h0 = (acc[mt][nt][0] - mlo_mu) * mlo_in * g0 + bb0;
                float h1 = (acc[mt][nt][1] - mlo_mu) * mlo_in * g1 + bb1;
                float h2v = (acc[mt][nt][2] - mhi_mu) * mhi_in * g0 + bb0;
                float h3 = (acc[mt][nt][3] - mhi_mu) * mhi_in * g1 + bb1;
                *(__nv_bfloat162*)&out2[base_lo[mt] + n] =
                    __nv_bfloat162(__float2bfloat16(h0), __float2bfloat16(h1));
                *(__nv_bfloat162*)&out2[base_hi[mt] + n] =
                    __nv_bfloat162(__float2bfloat16(h2v), __float2bfloat16(h3));
            }
        }
        return;
    }

#pragma unroll
    for (int mt = 0; mt < 4; mt++) {
        int mlo = m0 + wm + mt * 16 + gid;
        int mhi = mlo + 8;
        size_t base_lo = (size_t)mlo * N;
        size_t base_hi = (size_t)mhi * N;
#pragma unroll
        for (int nt = 0; nt < 4; nt++) {
            int n = n0 + wn + nt * 8 + 2 * tg;
            float b0 = bias[n], b1 = bias[n + 1];
            float v0 = acc[mt][nt][0] + b0, v1 = acc[mt][nt][1] + b1;
            float v2 = acc[mt][nt][2] + b0, v3 = acc[mt][nt][3] + b1;
            bf16* C = (bf16*)Cv;
            *(__nv_bfloat162*)&C[base_lo + n] =
                __nv_bfloat162(__float2bfloat16(v0), __float2bfloat16(v1));
            *(__nv_bfloat162*)&C[base_hi + n] =
                __nv_bfloat162(__float2bfloat16(v2), __float2bfloat16(v3));
        }
    }
}

// ---------------- fused MLP: fc1 + GELU (smem) + fc2 + residual -------------------------
#define SMEM_MLP 104448
__global__ void __launch_bounds__(256) mlp_fused(const bf16* __restrict__ h2,
                                                 const bf16* __restrict__ w1,
                                                 const float* __restrict__ b1,
                                                 const bf16* __restrict__ w2,
                                                 const float* __restrict__ b2f,
                                                 const float* __restrict__ x1,
                                                 float* __restrict__ out) {
    extern __shared__ char sm_[];
    bf16* Ah  = (bf16*)sm_;
    bf16* Hid = (bf16*)(sm_ + 17408);
    bf16* Bst = (bf16*)(sm_ + 83968);

    const int tid  = threadIdx.x;
    const int m0   = blockIdx.x * 64;
    const int warp = tid >> 5, lane = tid & 31;
    const int wm   = (warp & 1) * 32;
    const int wn   = (warp >> 1) * 32;
    const int lr16 = lane & 15, lh = lane >> 4;
    const int bt   = lane >> 3, brw = lane & 7;
    const int gid  = lane >> 2, tg  = lane & 3;
    const int lrow = tid >> 1, lcol = (tid & 1) * 16;

    uint32_t bD[2];
    bD[0] = (uint32_t)__cvta_generic_to_shared(&Bst[lrow * 40 + lcol]);
    bD[1] = (uint32_t)__cvta_generic_to_shared(&Bst[5120 + lrow * 40 + lcol]);

    {
        int q = tid;
#pragma unroll
        for (int i = 0; i < 4; i++, q += 256) {
            int r = q >> 4, c = (q & 15) * 8;
            cp16((uint32_t)__cvta_generic_to_shared(&Ah[r * 136 + c]),
                 h2 + (size_t)(m0 + r) * 128 + c);
        }
    }
    {
        const bf16* bp = w1 + (size_t)lrow * 128 + lcol;
        cp16(bD[0], bp); cp16(bD[0] + 16, bp + 8);
    }
    cp_commit();

    int buf = 0;
    for (int nc = 0; nc < 4; nc++) {
        float acc[2][4][4];
#pragma unroll
        for (int i = 0; i < 2; i++)
#pragma unroll
            for (int j = 0; j < 4; j++)
#pragma unroll
                for (int k = 0; k < 4; k++) acc[i][j][k] = 0.f;

        for (int it = 0; it < 4; it++) {
            cp_wait0();
            __syncthreads();
            int nn = nc, ni = it + 1;
            if (ni == 4) { nn++; ni = 0; }
            if (nn < 4) {
                const bf16* bp = w1 + (size_t)(nn * 128 + lrow) * 128 + ni * 32 + lcol;
                cp16(bD[buf ^ 1], bp); cp16(bD[buf ^ 1] + 16, bp + 8);
                cp_commit();
            }
            const bf16* Bbuf = Bst + buf * 5120;
#pragma unroll
            for (int kk = 0; kk < 32; kk += 16) {
                uint32_t af[2][4], bfr[4][2];
#pragma unroll
                for (int mt = 0; mt < 2; mt++)
                    ldsm4(af[mt], &Ah[(wm + mt * 16 + lr16) * 136 + it * 32 + kk + lh * 8]);
#pragma unroll
                for (int ntp = 0; ntp < 2; ntp++) {
                    uint32_t tmp[4];
                    int rn = wn + ntp * 16 + (bt >> 1) * 8 + brw;
                    ldsm4(tmp, &Bbuf[rn * 40 + kk + (bt & 1) * 8]);
                    bfr[ntp * 2][0]     = tmp[0]; bfr[ntp * 2][1]     = tmp[1];
                    bfr[ntp * 2 + 1][0] = tmp[2]; bfr[ntp * 2 + 1][1] = tmp[3];
                }
#pragma unroll
                for (int mt = 0; mt < 2; mt++)
#pragma unroll
                    for (int nt = 0; nt < 4; nt++)
                        mma_bf16(acc[mt][nt], af[mt], bfr[nt]);
            }
            buf ^= 1;
        }
#pragma unroll
        for (int mt = 0; mt < 2; mt++) {
            int rlo = wm + mt * 16 + gid, rhi = rlo + 8;
#pragma unroll
            for (int nt = 0; nt < 4; nt++) {
                int n = wn + nt * 8 + 2 * tg;
                float bb0 = b1[nc * 128 + n], bb1 = b1[nc * 128 + n + 1];
                float v0 = acc[mt][nt][0] + bb0, v1 = acc[mt][nt][1] + bb1;
                float v2 = acc[mt][nt][2] + bb0, v3 = acc[mt][nt][3] + bb1;
                v0 = 0.5f * v0 * (1.0f + erff(v0 * 0.70710678118654752f));
                v1 = 0.5f * v1 * (1.0f + erff(v1 * 0.70710678118654752f));
                v2 = 0.5f * v2 * (1.0f + erff(v2 * 0.70710678118654752f));
                v3 = 0.5f * v3 * (1.0f + erff(v3 * 0.70710678118654752f));
                *(uint32_t*)&Hid[rlo * 520 + nc * 128 + n] = pack_bf(v0, v1);
                *(uint32_t*)&Hid[rhi * 520 + nc * 128 + n] = pack_bf(v2, v3);
            }
        }
    }
    __syncthreads();

    {
        const bf16* bp = w2 + (size_t)lrow * 512 + lcol;
        cp16(bD[buf], bp); cp16(bD[buf] + 16, bp + 8);
        cp_commit();
    }
    float acc[2][4][4];
#pragma unroll
    for (int i = 0; i < 2; i++)
#pragma unroll
        for (int j = 0; j < 4; j++)
#pragma unroll
            for (int k = 0; k < 4; k++) acc[i][j][k] = 0.f;

    for (int it = 0; it < 16; it++) {
        cp_wait0();
        __syncthreads();
        if (it + 1 < 16) {
            const bf16* bp = w2 + (size_t)lrow * 512 + (it + 1) * 32 + lcol;
            cp16(bD[buf ^ 1], bp); cp16(bD[buf ^ 1] + 16, bp + 8);
            cp_commit();
        }
        const bf16* Bbuf = Bst + buf * 5120;
#pragma unroll
        for (int kk = 0; kk < 32; kk += 16) {
            uint32_t af[2][4], bfr[4][2];
#pragma unroll
            for (int mt = 0; mt < 2; mt++)
                ldsm4(af[mt], &Hid[(wm + mt * 16 + lr16) * 520 + it * 32 + kk + lh * 8]);
#pragma unroll
            for (int ntp = 0; ntp < 2; ntp++) {
                uint32_t tmp[4];
                int rn = wn + ntp * 16 + (bt >> 1) * 8 + brw;
                ldsm4(tmp, &Bbuf[rn * 40 + kk + (bt & 1) * 8]);
                bfr[ntp * 2][0]     = tmp[0]; bfr[ntp * 2][1]     = tmp[1];
                bfr[ntp * 2 + 1][0] = tmp[2]; bfr[ntp * 2 + 1][1] = tmp[3];
            }
#pragma unroll
            for (int mt = 0; mt < 2; mt++)
#pragma unroll
                for (int nt = 0; nt < 4; nt++)
                    mma_bf16(acc[mt][nt], af[mt], bfr[nt]);
        }
        buf ^= 1;
    }

#pragma unroll
    for (int mt = 0; mt < 2; mt++) {
        int rlo = m0 + wm + mt * 16 + gid, rhi = rlo + 8;
#pragma unroll
        for (int nt = 0; nt < 4; nt++) {
            int n = wn + nt * 8 + 2 * tg;
            float bb0 = b2f[n], bb1 = b2f[n + 1];
            float v0 = acc[mt][nt][0] + bb0 + x1[(size_t)rlo * 128 + n];
            float v1 = acc[mt][nt][1] + bb1 + x1[(size_t)rlo * 128 + n + 1];
            float v2 = acc[mt][nt][2] + bb0 + x1[(size_t)rhi * 128 + n];
            float v3 = acc[mt][nt][3] + bb1 + x1[(size_t)rhi * 128 + n + 1];
            *(float2*)&out[(size_t)rlo * 128 + n] = make_float2(v0, v1);
            *(float2*)&out[(size_t)rhi * 128 + n] = make_float2(v2, v3);
        }
    }
}

// ---------------- tensor-core windowed attention --------------------------------------
#define AT_S 40   // Q/K/V smem row stride (bf16)
__global__ void __launch_bounds__(128) attn_mma(const bf16* __restrict__ qkv,
                                                const float* __restrict__ biasb,
                                                bf16* __restrict__ out) {
    const int wi  = blockIdx.x;
    const int hb  = blockIdx.y;
    const int tid = threadIdx.x;
    const int warp = tid >> 5, lane = tid & 31;
    const int hh   = warp >> 1;
    const int half = warp & 1;
    const int r0   = half * 32;
    const int h    = hb * 2 + hh;

    __shared__ bf16 Qs[2][64 * AT_S];
    __shared__ bf16 Ks[2][64 * AT_S];
    __shared__ bf16 Vs[2][64 * AT_S];

    for (int i = tid; i < 600; i += 128) {
        int lh2 = i / 300, rr = i % 300;
        int row = 49 + rr / 20, d2 = rr % 20;
        ((uint32_t*)&Vs[lh2][row * AT_S])[d2] = 0;
    }

    for (int idx = tid; idx < NWIN * 8; idx += 128) {
        int t  = idx >> 3;
        int c8 = (idx & 7) * 8;
        int lh2 = c8 >> 5;
        int d  = c8 & 31;
        const bf16* base = qkv + (size_t)(wi * NWIN + t) * 384 + hb * 64 + c8;
        *(uint4*)&Qs[lh2][t * AT_S + d] = *(const uint4*)(base);
        *(uint4*)&Ks[lh2][t * AT_S + d] = *(const uint4*)(base + 128);
        *(uint4*)&Vs[lh2][t * AT_S + d] = *(const uint4*)(base + 256);
    }
    __syncthreads();

    const int lr16 = lane & 15, lh = lane >> 4;
    const int bt = lane >> 3, brw = lane & 7;
    const int gid = lane >> 2, tg = lane & 3;

    float S[2][8][4];
#pragma unroll
    for (int i = 0; i < 2; i++)
#pragma unroll
        for (int j = 0; j < 8; j++)
#pragma unroll
            for (int k = 0; k < 4; k++) S[i][j][k] = 0.f;

#pragma unroll
    for (int kk = 0; kk < 32; kk += 16) {
        uint32_t af[2][4], bfr[8][2];
        ldsm4(af[0], &Qs[hh][(r0 + lr16)      * AT_S + kk + lh * 8]);
        ldsm4(af[1], &Qs[hh][(r0 + 16 + lr16) * AT_S + kk + lh * 8]);
#pragma unroll
        for (int ntp = 0; ntp < 4; ntp++) {
            uint32_t tmp[4];
            int rn = ntp * 16 + (bt >> 1) * 8 + brw;
            ldsm4(tmp, &Ks[hh][rn * AT_S + kk + (bt & 1) * 8]);
            bfr[ntp * 2][0]     = tmp[0]; bfr[ntp * 2][1]     = tmp[1];
            bfr[ntp * 2 + 1][0] = tmp[2]; bfr[ntp * 2 + 1][1] = tmp[3];
        }
#pragma unroll
        for (int mt = 0; mt < 2; mt++)
#pragma unroll
            for (int nt = 0; nt < 8; nt++)
                mma_bf16(S[mt][nt], af[mt], bfr[nt]);
    }

    const float scale = 0.17677669529663687f;
#pragma unroll
    for (int mt = 0; mt < 2; mt++) {
        int tlo = r0 + mt * 16 + gid;
        int thi = tlo + 8;
        float mlo = -1e30f, mhi = -1e30f;
#pragma unroll
        for (int nt = 0; nt < 8; nt++) {
            int m = nt * 8 + 2 * tg;
            float2 blo = make_float2(0.f, 0.f), bhi = make_float2(0.f, 0.f);
            if (m < NWIN) {
                blo = *(const float2*)&biasb[(h * 64 + tlo) * 50 + m];
                bhi = *(const float2*)&biasb[(h * 64 + thi) * 50 + m];
            }
            float s0 = S[mt][nt][0] * scale + blo.x;
            float s1 = S[mt][nt][1] * scale + blo.y;
            float s2 = S[mt][nt][2] * scale + bhi.x;
            float s3 = S[mt][nt][3] * scale + bhi.y;
            if (m >= NWIN)     { s0 = -1e30f; s2 = -1e30f; }
            if (m + 1 >= NWIN) { s1 = -1e30f; s3 = -1e30f; }
            S[mt][nt][0] = s0; S[mt][nt][1] = s1; S[mt][nt][2] = s2; S[mt][nt][3] = s3;
            mlo = fmaxf(mlo, fmaxf(s0, s1));
            mhi = fmaxf(mhi, fmaxf(s2, s3));
        }
        mlo = fmaxf(mlo, __shfl_xor_sync(0xffffffffu, mlo, 1));
        mlo = fmaxf(mlo, __shfl_xor_sync(0xffffffffu, mlo, 2));
        mhi = fmaxf(mhi, __shfl_xor_sync(0xffffffffu, mhi, 1));
        mhi = fmaxf(mhi, __shfl_xor_sync(0xffffffffu, mhi, 2));
        float slo = 0.f, shi = 0.f;
#pragma unroll
        for (int nt = 0; nt < 8; nt++) {
            float e0 = __expf(S[mt][nt][0] - mlo);
            float e1 = __expf(S[mt][nt][1] - mlo);
            float e2 = __expf(S[mt][nt][2] - mhi);
            float e3 = __expf(S[mt][nt][3] - mhi);
            S[mt][nt][0] = e0; S[mt][nt][1] = e1; S[mt][nt][2] = e2; S[mt][nt][3] = e3;
            slo += e0 + e1; shi += e2 + e3;
        }
        slo += __shfl_xor_sync(0xffffffffu, slo, 1);
        slo += __shfl_xor_sync(0xffffffffu, slo, 2);
        shi += __shfl_xor_sync(0xffffffffu, shi, 1);
        shi += __shfl_xor_sync(0xffffffffu, shi, 2);
        float ilo = 1.0f / slo, ihi = 1.0f / shi;
#pragma unroll
        for (int nt = 0; nt < 8; nt++) {
            S[mt][nt][0] *= ilo; S[mt][nt][1] *= ilo;
            S[mt][nt][2] *= ihi; S[mt][nt][3] *= ihi;
        }
    }

    uint32_t pa[2][4][4];
#pragma unroll
    for (int mt = 0; mt < 2; mt++)
#pragma unroll
        for (int ks = 0; ks < 4; ks++) {
            pa[mt][ks][0] = pack_bf(S[mt][2 * ks][0],     S[mt][2 * ks][1]);
            pa[mt][ks][1] = pack_bf(S[mt][2 * ks][2],     S[mt][2 * ks][3]);
            pa[mt][ks][2] = pack_bf(S[mt][2 * ks + 1][0], S[mt][2 * ks + 1][1]);
            pa[mt][ks][3] = pack_bf(S[mt][2 * ks + 1][2], S[mt][2 * ks + 1][3]);
        }

    float O[2][4][4];
#pragma unroll
    for (int i = 0; i < 2; i++)
#pragma unroll
        for (int j = 0; j < 4; j++)
#pragma unroll
            for (int k = 0; k < 4; k++) O[i][j][k] = 0.f;

#pragma unroll
    for (int ks = 0; ks < 4; ks++) {
        uint32_t bv[4][2];
#pragma unroll
        for (int np = 0; np < 2; np++) {
            uint32_t tmp[4];
            int row = ks * 16 + (bt & 1) * 8 + brw;
            int col = np * 16 + (bt >> 1) * 8;
            ldsm4t(tmp, &Vs[hh][row * AT_S + col]);
            bv[np * 2][0]     = tmp[0]; bv[np * 2][1]     = tmp[1];
            bv[np * 2 + 1][0] = tmp[2]; bv[np * 2 + 1][1] = tmp[3];
        }
#pragma unroll
        for (int mt = 0; mt < 2; mt++)
#pragma unroll
            for (int nd = 0; nd < 4; nd++)
                mma_bf16(O[mt][nd], pa[mt][ks], bv[nd]);
    }

#pragma unroll
    for (int mt = 0; mt < 2; mt++) {
        int tlo = r0 + mt * 16 + gid;
        int thi = tlo + 8;
#pragma unroll
        for (int nd = 0; nd < 4; nd++) {
            int d = nd * 8 + 2 * tg;
            if (tlo < NWIN)
                *(__nv_bfloat162*)&out[(size_t)(wi * NWIN + tlo) * CDIM + h * HD + d] =
                    __nv_bfloat162(__float2bfloat16(O[mt][nd][0]), __float2bfloat16(O[mt][nd][1]));
            if (thi < NWIN)
                *(__nv_bfloat162*)&out[(size_t)(wi * NWIN + thi) * CDIM + h * HD + d] =
                    __nv_bfloat162(__float2bfloat16(O[mt][nd][2]), __float2bfloat16(O[mt][nd][3]));
        }
    }
}

// ---------------- launch ----------------
extern "C" void kernel_launch(void* const* d_in, const int* in_sizes, int n_in,
                              void* d_out, int out_size) {
    const float* x     = (const float*)d_in[0];
    const float* n1g   = (const float*)d_in[1];
    const float* n1b   = (const float*)d_in[2];
    const float* qkvw  = (const float*)d_in[3];
    const float* qkvb  = (const float*)d_in[4];
    const float* rpb   = (const float*)d_in[5];
    const float* projw = (const float*)d_in[6];
    const float* projb = (const float*)d_in[7];
    const float* n2g   = (const float*)d_in[8];
    const float* n2b   = (const float*)d_in[9];
    const float* fc1w  = (const float*)d_in[10];
    const float* fc1b  = (const float*)d_in[11];
    const float* fc2w  = (const float*)d_in[12];
    const float* fc2b  = (const float*)d_in[13];
    const int*   ridx  = (const int*)  d_in[14];
    float* out = (float*)d_out;

    bf16 *xw, *qkv, *attn, *h2, *wb;
    float *x1, *biasb;
    cudaGetSymbolAddress((void**)&xw,    g_xw);
    cudaGetSymbolAddress((void**)&qkv,   g_qkv);
    cudaGetSymbolAddress((void**)&attn,  g_attn);
    cudaGetSymbolAddress((void**)&x1,    g_x1);
    cudaGetSymbolAddress((void**)&h2,    g_h2);
    cudaGetSymbolAddress((void**)&wb,    g_wb);
    cudaGetSymbolAddress((void**)&biasb, g_bias);

    bf16* qkvw_b  = wb;
    bf16* projw_b = wb + 49152;
    bf16* fc1w_b  = wb + 65536;
    bf16* fc2w_b  = wb + 131072;

    cudaFuncSetAttribute(mlp_fused, cudaFuncAttributeMaxDynamicSharedMemorySize, SMEM_MLP);

    // 0) weight conversion + bias table (one launch)
    setup_kernel<<<243, 256>>>(qkvw, projw, fc1w, fc2w, wb, rpb, ridx, biasb);

    // 1) LN1 + cyclic shift + window partition (bf16 out, vectorized)
    ln_kernel<<<MROWS / 8, 256>>>(x, n1g, n1b, xw);

    // 2) QKV projection: [M,128] @ [384,128]^T -> bf16
    bgemm<0><<<dim3(MROWS / BM, 3), 256>>>(xw, qkvw_b, qkvb, nullptr, qkv,
                                           nullptr, nullptr, nullptr,
                                           MROWS, 3 * CDIM, CDIM);

    // 3) tensor-core windowed attention -> bf16
    attn_mma<<<dim3(BATCH * 64, 2), 128>>>(qkv, biasb, attn);

    // 4) proj + window reverse + unshift + residual -> x1 fp32; fused LN2 -> h2 bf16
    bgemm<3><<<dim3(MROWS / BM, 1), 256>>>(attn, projw_b, projb, x, x1,
                                           n2g, n2b, h2,
                                           MROWS, CDIM, CDIM);

    // 5) fused MLP: fc1 + GELU + fc2 + residual -> out fp32
    mlp_fused<<<MROWS / 64, 256, SMEM_MLP>>>(h2, fc1w_b, fc1b, fc2w_b, fc2b, x1, out);
}

// round 17
// speedup vs baseline: 1.2026x; 1.0356x over previous
#include <cuda_runtime.h>
#include <cuda_bf16.h>
#include <math.h>
#include <stdint.h>

// ---------------- problem constants ----------------
#define BATCH 32
#define HDIM  56
#define WDIM  56
#define CDIM  128
#define NHEAD 4
#define WS    7
#define SS    3
#define LTOK  (HDIM*WDIM)          // 3136
#define NWIN  (WS*WS)              // 49
#define HD    (CDIM/NHEAD)         // 32
#define MROWS (BATCH*LTOK)         // 100352

#define BM 128
#define BN 128
#define BK 32
#define LDB 40   // smem row stride in bf16 elems (80B) -> conflict-free ldmatrix

typedef __nv_bfloat16 bf16;

// ---------------- scratch (device globals; no allocation) ----------------
__device__ bf16  g_xw  [(size_t)MROWS * CDIM];
__device__ bf16  g_qkv [(size_t)MROWS * 3 * CDIM];
__device__ bf16  g_attn[(size_t)MROWS * CDIM];
__device__ float g_x1  [(size_t)MROWS * CDIM];
__device__ bf16  g_h2  [(size_t)MROWS * CDIM];
__device__ bf16  g_wb  [196608];       // qkv(49152) | proj(16384) | fc1(65536) | fc2(65536)
__device__ float g_bias[4 * 64 * 50];  // padded rel-pos bias [h][t(64)][m(50)]

// ---------------- helpers ----------------
__device__ __forceinline__ void ldsm4(uint32_t* r, const bf16* p) {
    uint32_t addr = (uint32_t)__cvta_generic_to_shared(p);
    asm volatile("ldmatrix.sync.aligned.m8n8.x4.shared.b16 {%0,%1,%2,%3}, [%4];"
        : "=r"(r[0]), "=r"(r[1]), "=r"(r[2]), "=r"(r[3]) : "r"(addr));
}

__device__ __forceinline__ void ldsm4t(uint32_t* r, const bf16* p) {
    uint32_t addr = (uint32_t)__cvta_generic_to_shared(p);
    asm volatile("ldmatrix.sync.aligned.m8n8.x4.trans.shared.b16 {%0,%1,%2,%3}, [%4];"
        : "=r"(r[0]), "=r"(r[1]), "=r"(r[2]), "=r"(r[3]) : "r"(addr));
}

__device__ __forceinline__ void mma_bf16(float* d, const uint32_t* a, const uint32_t* b) {
    asm volatile("mma.sync.aligned.m16n8k16.row.col.f32.bf16.bf16.f32 "
        "{%0,%1,%2,%3}, {%4,%5,%6,%7}, {%8,%9}, {%0,%1,%2,%3};"
        : "+f"(d[0]), "+f"(d[1]), "+f"(d[2]), "+f"(d[3])
        : "r"(a[0]), "r"(a[1]), "r"(a[2]), "r"(a[3]), "r"(b[0]), "r"(b[1]));
}

__device__ __forceinline__ uint32_t pack_bf(float lo, float hi) {
    uint32_t r; asm("cvt.rn.bf16x2.f32 %0, %1, %2;" : "=r"(r) : "f"(hi), "f"(lo)); return r;
}

__device__ __forceinline__ void cp16(uint32_t saddr, const void* g) {
    asm volatile("cp.async.cg.shared.global [%0], [%1], 16;" :: "r"(saddr), "l"(g));
}
__device__ __forceinline__ void cp_commit() { asm volatile("cp.async.commit_group;"); }
__device__ __forceinline__ void cp_wait0()  { asm volatile("cp.async.wait_group 0;"); }

// window-reverse + unshift scatter base for token row m (window layout -> image layout)
__device__ __forceinline__ uint32_t win_scatter(int m) {
    int wi = m / NWIN, t = m % NWIN;
    int bb = wi >> 6, wh = (wi >> 3) & 7, ww = wi & 7;
    int ih = t / WS, jw = t % WS;
    int hr = wh * WS + ih + SS; if (hr >= HDIM) hr -= HDIM;
    int wc = ww * WS + jw + SS; if (wc >= WDIM) wc -= WDIM;
    return ((uint32_t)(bb * HDIM + hr) * WDIM + wc) * CDIM;
}

// ---------------- fused LN1 + setup (weight cvt + bias table), one launch ---------------
// blocks [0, 12544): LN1 over 8 rows each; blocks [12544, 12787): setup work.
#define LN_BLOCKS (MROWS / 8)
__global__ void __launch_bounds__(256) ln_setup(const float* __restrict__ x,
                                                const float* __restrict__ g,
                                                const float* __restrict__ b,
                                                bf16* __restrict__ out,
                                                const float* __restrict__ w0,
                                                const float* __restrict__ w1,
                                                const float* __restrict__ w2,
                                                const float* __restrict__ w3,
                                                bf16* __restrict__ outw,
                                                const float* __restrict__ rpb,
                                                const int* __restrict__ rel_idx,
                                                float* __restrict__ biasb) {
    if (blockIdx.x >= LN_BLOCKS) {
        int t = (blockIdx.x - LN_BLOCKS) * 256 + threadIdx.x;
        if (t < 49152) {
            int i = t * 4;
            const float* src; int j = i;
            if (i < 49152)       { src = w0; }
            else if (i < 65536)  { src = w1; j = i - 49152; }
            else if (i < 131072) { src = w2; j = i - 65536; }
            else                 { src = w3; j = i - 131072; }
            float4 v = *(const float4*)(src + j);
            outw[i]     = __float2bfloat16(v.x);
            outw[i + 1] = __float2bfloat16(v.y);
            outw[i + 2] = __float2bfloat16(v.z);
            outw[i + 3] = __float2bfloat16(v.w);
        } else {
            int i = t - 49152;   // 0..12799
            if (i < 12800) {
                int h = i / 3200, r = i % 3200, tt = r / 50, m = r % 50;
                float v = 0.f;
                if (tt < NWIN && m < NWIN) v = rpb[rel_idx[tt * NWIN + m] * NHEAD + h];
                biasb[i] = v;
            }
        }
        return;
    }

    int gw   = (blockIdx.x * blockDim.x + threadIdx.x) >> 5;
    int lane = threadIdx.x & 31;

    const float* xp = x + win_scatter(gw);
    float4 v  = *(const float4*)(xp + lane * 4);
    float4 gg = *(const float4*)(g + lane * 4);
    float4 bb = *(const float4*)(b + lane * 4);

    float mu = v.x + v.y + v.z + v.w;
#pragma unroll
    for (int o = 16; o; o >>= 1) mu += __shfl_xor_sync(0xffffffffu, mu, o);
    mu *= (1.0f / 128.0f);
    float d0 = v.x - mu, d1 = v.y - mu, d2 = v.z - mu, d3 = v.w - mu;
    float var = d0 * d0 + d1 * d1 + d2 * d2 + d3 * d3;
#pragma unroll
    for (int o = 16; o; o >>= 1) var += __shfl_xor_sync(0xffffffffu, var, o);
    float inv = rsqrtf(var * (1.0f / 128.0f) + 1e-5f);

    uint32_t p0 = pack_bf(d0 * inv * gg.x + bb.x, d1 * inv * gg.y + bb.y);
    uint32_t p1 = pack_bf(d2 * inv * gg.z + bb.z, d3 * inv * gg.w + bb.w);
    *(uint2*)&out[(size_t)gw * CDIM + lane * 4] = make_uint2(p0, p1);
}

// ---------------- bf16 tensor-core GEMM, 2-stage cp.async, ONE barrier/iter -------------
// EPI 0: bias only -> bf16 out
// EPI 3: bias + window scatter + residual + fused LN2 -> fp32 x1 AND bf16 h2 (N==128)
template<int EPI>
__global__ void __launch_bounds__(256) bgemm(const bf16* __restrict__ A,
                                             const bf16* __restrict__ Bw,
                                             const float* __restrict__ bias,
                                             const float* __restrict__ res,
                                             void* __restrict__ Cv,
                                             const float* __restrict__ g2,
                                             const float* __restrict__ b2,
                                             bf16* __restrict__ out2,
                                             int M, int N, int K) {
    __shared__ bf16 As[2][BM * LDB];
    __shared__ bf16 Bs[2][BN * LDB];

    const int tid  = threadIdx.x;
    const int m0   = blockIdx.x * BM;
    const int n0   = blockIdx.y * BN;
    const int warp = tid >> 5, lane = tid & 31;
    const int wm   = (warp & 1) * 64;
    const int wn   = (warp >> 1) * 32;

    const int lrow = tid >> 1;
    const int lcol = (tid & 1) * 16;
    const bf16* Ag = A  + (size_t)(m0 + lrow) * K + lcol;
    const bf16* Bg = Bw + (size_t)(n0 + lrow) * K + lcol;

    uint32_t aDst[2], bDst[2];
    aDst[0] = (uint32_t)__cvta_generic_to_shared(&As[0][lrow * LDB + lcol]);
    aDst[1] = (uint32_t)__cvta_generic_to_shared(&As[1][lrow * LDB + lcol]);
    bDst[0] = (uint32_t)__cvta_generic_to_shared(&Bs[0][lrow * LDB + lcol]);
    bDst[1] = (uint32_t)__cvta_generic_to_shared(&Bs[1][lrow * LDB + lcol]);

    float acc[4][4][4];
#pragma unroll
    for (int i = 0; i < 4; i++)
#pragma unroll
        for (int j = 0; j < 4; j++)
#pragma unroll
            for (int k = 0; k < 4; k++) acc[i][j][k] = 0.f;

    const int NIT = K / BK;
    cp16(aDst[0], Ag);          cp16(aDst[0] + 16, Ag + 8);
    cp16(bDst[0], Bg);          cp16(bDst[0] + 16, Bg + 8);
    cp_commit();

    const int lr16 = lane & 15, lh = lane >> 4;
    const int bt   = lane >> 3, brw = lane & 7;

    for (int it = 0; it < NIT; it++) {
        const int cur = it & 1;
        cp_wait0();
        __syncthreads();
        if (it + 1 < NIT) {
            const int nxt = cur ^ 1;
            const bf16* an = Ag + (it + 1) * BK;
            const bf16* bn = Bg + (it + 1) * BK;
            cp16(aDst[nxt], an);      cp16(aDst[nxt] + 16, an + 8);
            cp16(bDst[nxt], bn);      cp16(bDst[nxt] + 16, bn + 8);
            cp_commit();
        }
#pragma unroll
        for (int kk = 0; kk < BK; kk += 16) {
            uint32_t af[4][4], bfr[4][2];
#pragma unroll
            for (int mt = 0; mt < 4; mt++)
                ldsm4(af[mt], &As[cur][(wm + mt * 16 + lr16) * LDB + kk + lh * 8]);
#pragma unroll
            for (int ntp = 0; ntp < 2; ntp++) {
                uint32_t tmp[4];
                int rn = wn + ntp * 16 + (bt >> 1) * 8 + brw;
                int ck = kk + (bt & 1) * 8;
                ldsm4(tmp, &Bs[cur][rn * LDB + ck]);
                bfr[ntp * 2][0]     = tmp[0]; bfr[ntp * 2][1]     = tmp[1];
                bfr[ntp * 2 + 1][0] = tmp[2]; bfr[ntp * 2 + 1][1] = tmp[3];
            }
#pragma unroll
            for (int mt = 0; mt < 4; mt++)
#pragma unroll
                for (int nt = 0; nt < 4; nt++)
                    mma_bf16(acc[mt][nt], af[mt], bfr[nt]);
        }
    }
    __syncthreads();

    const int gid = lane >> 2, tg = lane & 3;

    if (EPI == 3) {
        float* red_s = (float*)&As[0][0];
        float* red_q = red_s + 512;
        float* mu_s  = red_q + 512;
        float* inv_s = mu_s + 128;
        const int wnidx = warp >> 1;
        float* x1 = (float*)Cv;

        uint32_t base_lo[4], base_hi[4];
        float psum[4][2], psq[4][2];
#pragma unroll
        for (int mt = 0; mt < 4; mt++) {
            int mlo = m0 + wm + mt * 16 + gid;
            base_lo[mt] = win_scatter(mlo);
            base_hi[mt] = win_scatter(mlo + 8);
            psum[mt][0] = psum[mt][1] = 0.f;
            psq[mt][0]  = psq[mt][1]  = 0.f;
#pragma unroll
            for (int nt = 0; nt < 4; nt++) {
                int n = wn + nt * 8 + 2 * tg;
                float b0 = bias[n], b1 = bias[n + 1];
                float v0 = acc[mt][nt][0] + b0 + res[base_lo[mt] + n];
                float v1 = acc[mt][nt][1] + b1 + res[base_lo[mt] + n + 1];
                float v2 = acc[mt][nt][2] + b0 + res[base_hi[mt] + n];
                float v3 = acc[mt][nt][3] + b1 + res[base_hi[mt] + n + 1];
                *(float2*)&x1[base_lo[mt] + n] = make_float2(v0, v1);
                *(float2*)&x1[base_hi[mt] + n] = make_float2(v2, v3);
                acc[mt][nt][0] = v0; acc[mt][nt][1] = v1;
                acc[mt][nt][2] = v2; acc[mt][nt][3] = v3;
                psum[mt][0] += v0 + v1;          psum[mt][1] += v2 + v3;
                psq[mt][0]  += v0 * v0 + v1 * v1; psq[mt][1] += v2 * v2 + v3 * v3;
            }
        }
#pragma unroll
        for (int mt = 0; mt < 4; mt++) {
#pragma unroll
            for (int hf = 0; hf < 2; hf++) {
                float s = psum[mt][hf], q = psq[mt][hf];
                s += __shfl_xor_sync(0xffffffffu, s, 1);
                s += __shfl_xor_sync(0xffffffffu, s, 2);
                q += __shfl_xor_sync(0xffffffffu, q, 1);
                q += __shfl_xor_sync(0xffffffffu, q, 2);
                if (tg == 0) {
                    int r = wm + mt * 16 + gid + hf * 8;
                    red_s[wnidx * 128 + r] = s;
                    red_q[wnidx * 128 + r] = q;
                }
            }
        }
        __syncthreads();
        if (tid < 128) {
            float s = red_s[tid] + red_s[128 + tid] + red_s[256 + tid] + red_s[384 + tid];
            float q = red_q[tid] + red_q[128 + tid] + red_q[256 + tid] + red_q[384 + tid];
            float mu = s * (1.0f / 128.0f);
            float var = q * (1.0f / 128.0f) - mu * mu;
            mu_s[tid]  = mu;
            inv_s[tid] = rsqrtf(var + 1e-5f);
        }
        __syncthreads();
#pragma unroll
        for (int mt = 0; mt < 4; mt++) {
            int rlo = wm + mt * 16 + gid, rhi = rlo + 8;
            float mlo_mu = mu_s[rlo], mlo_in = inv_s[rlo];
            float mhi_mu = mu_s[rhi], mhi_in = inv_s[rhi];
#pragma unroll
            for (int nt = 0; nt < 4; nt++) {
                int n = wn + nt * 8 + 2 * tg;
                float g0 = g2[n], g1 = g2[n + 1], bb0 = b2[n], bb1 = b2[n + 1];
                float h0 = (acc[mt][nt][0] - mlo_mu) * mlo_in * g0 + bb0;
                float h1 = (acc[mt][nt][1] - mlo_mu) * mlo_in * g1 + bb1;
                float h2v = (acc[mt][nt][2] - mhi_mu) * mhi_in * g0 + bb0;
                float h3 = (acc[mt][nt][3] - mhi_mu) * mhi_in * g1 + bb1;
                *(__nv_bfloat162*)&out2[base_lo[mt] + n] =
                    __nv_bfloat162(__float2bfloat16(h0), __float2bfloat16(h1));
                *(__nv_bfloat162*)&out2[base_hi[mt] + n] =
                    __nv_bfloat162(__float2bfloat16(h2v), __float2bfloat16(h3));
            }
        }
        return;
    }

#pragma unroll
    for (int mt = 0; mt < 4; mt++) {
        int mlo = m0 + wm + mt * 16 + gid;
        int mhi = mlo + 8;
        size_t base_lo = (size_t)mlo * N;
        size_t base_hi = (size_t)mhi * N;
#pragma unroll
        for (int nt = 0; nt < 4; nt++) {
            int n = n0 + wn + nt * 8 + 2 * tg;
            float b0 = bias[n], b1 = bias[n + 1];
            float v0 = acc[mt][nt][0] + b0, v1 = acc[mt][nt][1] + b1;
            float v2 = acc[mt][nt][2] + b0, v3 = acc[mt][nt][3] + b1;
            bf16* C = (bf16*)Cv;
            *(__nv_bfloat162*)&C[base_lo + n] =
                __nv_bfloat162(__float2bfloat16(v0), __float2bfloat16(v1));
            *(__nv_bfloat162*)&C[base_hi + n] =
                __nv_bfloat162(__float2bfloat16(v2), __float2bfloat16(v3));
        }
    }
}

// ---------------- fused MLP: fc1 + GELU (smem) + fc2 + residual -------------------------
#define SMEM_MLP 104448
__global__ void __launch_bounds__(256) mlp_fused(const bf16* __restrict__ h2,
                                                 const bf16* __restrict__ w1,
                                                 const float* __restrict__ b1,
                                                 const bf16* __restrict__ w2,
                                                 const float* __restrict__ b2f,
                                                 const float* __restrict__ x1,
                                                 float* __restrict__ out) {
    extern __shared__ char sm_[];
    bf16* Ah  = (bf16*)sm_;
    bf16* Hid = (bf16*)(sm_ + 17408);
    bf16* Bst = (bf16*)(sm_ + 83968);

    const int tid  = threadIdx.x;
    const int m0   = blockIdx.x * 64;
    const int warp = tid >> 5, lane = tid & 31;
    const int wm   = (warp & 1) * 32;
    const int wn   = (warp >> 1) * 32;
    const int lr16 = lane & 15, lh = lane >> 4;
    const int bt   = lane >> 3, brw = lane & 7;
    const int gid  = lane >> 2, tg  = lane & 3;
    const int lrow = tid >> 1, lcol = (tid & 1) * 16;

    uint32_t bD[2];
    bD[0] = (uint32_t)__cvta_generic_to_shared(&Bst[lrow * 40 + lcol]);
    bD[1] = (uint32_t)__cvta_generic_to_shared(&Bst[5120 + lrow * 40 + lcol]);

    {
        int q = tid;
#pragma unroll
        for (int i = 0; i < 4; i++, q += 256) {
            int r = q >> 4, c = (q & 15) * 8;
            cp16((uint32_t)__cvta_generic_to_shared(&Ah[r * 136 + c]),
                 h2 + (size_t)(m0 + r) * 128 + c);
        }
    }
    {
        const bf16* bp = w1 + (size_t)lrow * 128 + lcol;
        cp16(bD[0], bp); cp16(bD[0] + 16, bp + 8);
    }
    cp_commit();

    int buf = 0;
    for (int nc = 0; nc < 4; nc++) {
        float acc[2][4][4];
#pragma unroll
        for (int i = 0; i < 2; i++)
#pragma unroll
            for (int j = 0; j < 4; j++)
#pragma unroll
                for (int k = 0; k < 4; k++) acc[i][j][k] = 0.f;

        for (int it = 0; it < 4; it++) {
            cp_wait0();
            __syncthreads();
            int nn = nc, ni = it + 1;
            if (ni == 4) { nn++; ni = 0; }
            if (nn < 4) {
                const bf16* bp = w1 + (size_t)(nn * 128 + lrow) * 128 + ni * 32 + lcol;
                cp16(bD[buf ^ 1], bp); cp16(bD[buf ^ 1] + 16, bp + 8);
                cp_commit();
            }
            const bf16* Bbuf = Bst + buf * 5120;
#pragma unroll
            for (int kk = 0; kk < 32; kk += 16) {
                uint32_t af[2][4], bfr[4][2];
#pragma unroll
                for (int mt = 0; mt < 2; mt++)
                    ldsm4(af[mt], &Ah[(wm + mt * 16 + lr16) * 136 + it * 32 + kk + lh * 8]);
#pragma unroll
                for (int ntp = 0; ntp < 2; ntp++) {
                    uint32_t tmp[4];
                    int rn = wn + ntp * 16 + (bt >> 1) * 8 + brw;
                    ldsm4(tmp, &Bbuf[rn * 40 + kk + (bt & 1) * 8]);
                    bfr[ntp * 2][0]     = tmp[0]; bfr[ntp * 2][1]     = tmp[1];
                    bfr[ntp * 2 + 1][0] = tmp[2]; bfr[ntp * 2 + 1][1] = tmp[3];
                }
#pragma unroll
                for (int mt = 0; mt < 2; mt++)
#pragma unroll
                    for (int nt = 0; nt < 4; nt++)
                        mma_bf16(acc[mt][nt], af[mt], bfr[nt]);
            }
            buf ^= 1;
        }
#pragma unroll
        for (int mt = 0; mt < 2; mt++) {
            int rlo = wm + mt * 16 + gid, rhi = rlo + 8;
#pragma unroll
            for (int nt = 0; nt < 4; nt++) {
                int n = wn + nt * 8 + 2 * tg;
                float bb0 = b1[nc * 128 + n], bb1 = b1[nc * 128 + n + 1];
                float v0 = acc[mt][nt][0] + bb0, v1 = acc[mt][nt][1] + bb1;
                float v2 = acc[mt][nt][2] + bb0, v3 = acc[mt][nt][3] + bb1;
                v0 = 0.5f * v0 * (1.0f + erff(v0 * 0.70710678118654752f));
                v1 = 0.5f * v1 * (1.0f + erff(v1 * 0.70710678118654752f));
                v2 = 0.5f * v2 * (1.0f + erff(v2 * 0.70710678118654752f));
                v3 = 0.5f * v3 * (1.0f + erff(v3 * 0.70710678118654752f));
                *(uint32_t*)&Hid[rlo * 520 + nc * 128 + n] = pack_bf(v0, v1);
                *(uint32_t*)&Hid[rhi * 520 + nc * 128 + n] = pack_bf(v2, v3);
            }
        }
    }
    __syncthreads();

    {
        const bf16* bp = w2 + (size_t)lrow * 512 + lcol;
        cp16(bD[buf], bp); cp16(bD[buf] + 16, bp + 8);
        cp_commit();
    }
    float acc[2][4][4];
#pragma unroll
    for (int i = 0; i < 2; i++)
#pragma unroll
        for (int j = 0; j < 4; j++)
#pragma unroll
            for (int k = 0; k < 4; k++) acc[i][j][k] = 0.f;

    for (int it = 0; it < 16; it++) {
        cp_wait0();
        __syncthreads();
        if (it + 1 < 16) {
            const bf16* bp = w2 + (size_t)lrow * 512 + (it + 1) * 32 + lcol;
            cp16(bD[buf ^ 1], bp); cp16(bD[buf ^ 1] + 16, bp + 8);
            cp_commit();
        }
        const bf16* Bbuf = Bst + buf * 5120;
#pragma unroll
        for (int kk = 0; kk < 32; kk += 16) {
            uint32_t af[2][4], bfr[4][2];
#pragma unroll
            for (int mt = 0; mt < 2; mt++)
                ldsm4(af[mt], &Hid[(wm + mt * 16 + lr16) * 520 + it * 32 + kk + lh * 8]);
#pragma unroll
            for (int ntp = 0; ntp < 2; ntp++) {
                uint32_t tmp[4];
                int rn = wn + ntp * 16 + (bt >> 1) * 8 + brw;
                ldsm4(tmp, &Bbuf[rn * 40 + kk + (bt & 1) * 8]);
                bfr[ntp * 2][0]     = tmp[0]; bfr[ntp * 2][1]     = tmp[1];
                bfr[ntp * 2 + 1][0] = tmp[2]; bfr[ntp * 2 + 1][1] = tmp[3];
            }
#pragma unroll
            for (int mt = 0; mt < 2; mt++)
#pragma unroll
                for (int nt = 0; nt < 4; nt++)
                    mma_bf16(acc[mt][nt], af[mt], bfr[nt]);
        }
        buf ^= 1;
    }

#pragma unroll
    for (int mt = 0; mt < 2; mt++) {
        int rlo = m0 + wm + mt * 16 + gid, rhi = rlo + 8;
#pragma unroll
        for (int nt = 0; nt < 4; nt++) {
            int n = wn + nt * 8 + 2 * tg;
            float bb0 = b2f[n], bb1 = b2f[n + 1];
            float v0 = acc[mt][nt][0] + bb0 + x1[(size_t)rlo * 128 + n];
            float v1 = acc[mt][nt][1] + bb1 + x1[(size_t)rlo * 128 + n + 1];
            float v2 = acc[mt][nt][2] + bb0 + x1[(size_t)rhi * 128 + n];
            float v3 = acc[mt][nt][3] + bb1 + x1[(size_t)rhi * 128 + n + 1];
            *(float2*)&out[(size_t)rlo * 128 + n] = make_float2(v0, v1);
            *(float2*)&out[(size_t)rhi * 128 + n] = make_float2(v2, v3);
        }
    }
}

// ---------------- tensor-core windowed attention --------------------------------------
// cp.async QKV loads; softmax without max-subtraction (scores are O(1)).
#define AT_S 40   // Q/K/V smem row stride (bf16)
__global__ void __launch_bounds__(128) attn_mma(const bf16* __restrict__ qkv,
                                                const float* __restrict__ biasb,
                                                bf16* __restrict__ out) {
    const int wi  = blockIdx.x;
    const int hb  = blockIdx.y;
    const int tid = threadIdx.x;
    const int warp = tid >> 5, lane = tid & 31;
    const int hh   = warp >> 1;
    const int half = warp & 1;
    const int r0   = half * 32;
    const int h    = hb * 2 + hh;

    __shared__ bf16 Qs[2][64 * AT_S];
    __shared__ bf16 Ks[2][64 * AT_S];
    __shared__ bf16 Vs[2][64 * AT_S];

    // zero ONLY V padding rows 49..63
    for (int i = tid; i < 600; i += 128) {
        int lh2 = i / 300, rr = i % 300;
        int row = 49 + rr / 20, d2 = rr % 20;
        ((uint32_t*)&Vs[lh2][row * AT_S])[d2] = 0;
    }

    // QKV loads via cp.async (16B each)
    for (int idx = tid; idx < NWIN * 8; idx += 128) {
        int t  = idx >> 3;
        int c8 = (idx & 7) * 8;
        int lh2 = c8 >> 5;
        int d  = c8 & 31;
        const bf16* base = qkv + (size_t)(wi * NWIN + t) * 384 + hb * 64 + c8;
        cp16((uint32_t)__cvta_generic_to_shared(&Qs[lh2][t * AT_S + d]), base);
        cp16((uint32_t)__cvta_generic_to_shared(&Ks[lh2][t * AT_S + d]), base + 128);
        cp16((uint32_t)__cvta_generic_to_shared(&Vs[lh2][t * AT_S + d]), base + 256);
    }
    cp_commit();
    cp_wait0();
    __syncthreads();

    const int lr16 = lane & 15, lh = lane >> 4;
    const int bt = lane >> 3, brw = lane & 7;
    const int gid = lane >> 2, tg = lane & 3;

    float S[2][8][4];
#pragma unroll
    for (int i = 0; i < 2; i++)
#pragma unroll
        for (int j = 0; j < 8; j++)
#pragma unroll
            for (int k = 0; k < 4; k++) S[i][j][k] = 0.f;

#pragma unroll
    for (int kk = 0; kk < 32; kk += 16) {
        uint32_t af[2][4], bfr[8][2];
        ldsm4(af[0], &Qs[hh][(r0 + lr16)      * AT_S + kk + lh * 8]);
        ldsm4(af[1], &Qs[hh][(r0 + 16 + lr16) * AT_S + kk + lh * 8]);
#pragma unroll
        for (int ntp = 0; ntp < 4; ntp++) {
            uint32_t tmp[4];
            int rn = ntp * 16 + (bt >> 1) * 8 + brw;
            ldsm4(tmp, &Ks[hh][rn * AT_S + kk + (bt & 1) * 8]);
            bfr[ntp * 2][0]     = tmp[0]; bfr[ntp * 2][1]     = tmp[1];
            bfr[ntp * 2 + 1][0] = tmp[2]; bfr[ntp * 2 + 1][1] = tmp[3];
        }
#pragma unroll
        for (int mt = 0; mt < 2; mt++)
#pragma unroll
            for (int nt = 0; nt < 8; nt++)
                mma_bf16(S[mt][nt], af[mt], bfr[nt]);
    }

    // ---- scale + bias + exp (no max subtraction; masked -> 0) + normalize ----
    const float scale = 0.17677669529663687f;
#pragma unroll
    for (int mt = 0; mt < 2; mt++) {
        int tlo = r0 + mt * 16 + gid;
        int thi = tlo + 8;
        float slo = 0.f, shi = 0.f;
#pragma unroll
        for (int nt = 0; nt < 8; nt++) {
            int m = nt * 8 + 2 * tg;
            float2 blo = make_float2(0.f, 0.f), bhi = make_float2(0.f, 0.f);
            if (m < NWIN) {
                blo = *(const float2*)&biasb[(h * 64 + tlo) * 50 + m];
                bhi = *(const float2*)&biasb[(h * 64 + thi) * 50 + m];
            }
            float e0 = (m < NWIN)     ? __expf(S[mt][nt][0] * scale + blo.x) : 0.f;
            float e1 = (m + 1 < NWIN) ? __expf(S[mt][nt][1] * scale + blo.y) : 0.f;
            float e2 = (m < NWIN)     ? __expf(S[mt][nt][2] * scale + bhi.x) : 0.f;
            float e3 = (m + 1 < NWIN) ? __expf(S[mt][nt][3] * scale + bhi.y) : 0.f;
            S[mt][nt][0] = e0; S[mt][nt][1] = e1; S[mt][nt][2] = e2; S[mt][nt][3] = e3;
            slo += e0 + e1; shi += e2 + e3;
        }
        slo += __shfl_xor_sync(0xffffffffu, slo, 1);
        slo += __shfl_xor_sync(0xffffffffu, slo, 2);
        shi += __shfl_xor_sync(0xffffffffu, shi, 1);
        shi += __shfl_xor_sync(0xffffffffu, shi, 2);
        float ilo = 1.0f / slo, ihi = 1.0f / shi;
#pragma unroll
        for (int nt = 0; nt < 8; nt++) {
            S[mt][nt][0] *= ilo; S[mt][nt][1] *= ilo;
            S[mt][nt][2] *= ihi; S[mt][nt][3] *= ihi;
        }
    }

    uint32_t pa[2][4][4];
#pragma unroll
    for (int mt = 0; mt < 2; mt++)
#pragma unroll
        for (int ks = 0; ks < 4; ks++) {
            pa[mt][ks][0] = pack_bf(S[mt][2 * ks][0],     S[mt][2 * ks][1]);
            pa[mt][ks][1] = pack_bf(S[mt][2 * ks][2],     S[mt][2 * ks][3]);
            pa[mt][ks][2] = pack_bf(S[mt][2 * ks + 1][0], S[mt][2 * ks + 1][1]);
            pa[mt][ks][3] = pack_bf(S[mt][2 * ks + 1][2], S[mt][2 * ks + 1][3]);
        }

    float O[2][4][4];
#pragma unroll
    for (int i = 0; i < 2; i++)
#pragma unroll
        for (int j = 0; j < 4; j++)
#pragma unroll
            for (int k = 0; k < 4; k++) O[i][j][k] = 0.f;

#pragma unroll
    for (int ks = 0; ks < 4; ks++) {
        uint32_t bv[4][2];
#pragma unroll
        for (int np = 0; np < 2; np++) {
            uint32_t tmp[4];
            int row = ks * 16 + (bt & 1) * 8 + brw;
            int col = np * 16 + (bt >> 1) * 8;
            ldsm4t(tmp, &Vs[hh][row * AT_S + col]);
            bv[np * 2][0]     = tmp[0]; bv[np * 2][1]     = tmp[1];
            bv[np * 2 + 1][0] = tmp[2]; bv[np * 2 + 1][1] = tmp[3];
        }
#pragma unroll
        for (int mt = 0; mt < 2; mt++)
#pragma unroll
            for (int nd = 0; nd < 4; nd++)
                mma_bf16(O[mt][nd], pa[mt][ks], bv[nd]);
    }

#pragma unroll
    for (int mt = 0; mt < 2; mt++) {
        int tlo = r0 + mt * 16 + gid;
        int thi = tlo + 8;
#pragma unroll
        for (int nd = 0; nd < 4; nd++) {
            int d = nd * 8 + 2 * tg;
            if (tlo < NWIN)
                *(__nv_bfloat162*)&out[(size_t)(wi * NWIN + tlo) * CDIM + h * HD + d] =
                    __nv_bfloat162(__float2bfloat16(O[mt][nd][0]), __float2bfloat16(O[mt][nd][1]));
            if (thi < NWIN)
                *(__nv_bfloat162*)&out[(size_t)(wi * NWIN + thi) * CDIM + h * HD + d] =
                    __nv_bfloat162(__float2bfloat16(O[mt][nd][2]), __float2bfloat16(O[mt][nd][3]));
        }
    }
}

// ---------------- launch ----------------
extern "C" void kernel_launch(void* const* d_in, const int* in_sizes, int n_in,
                              void* d_out, int out_size) {
    const float* x     = (const float*)d_in[0];
    const float* n1g   = (const float*)d_in[1];
    const float* n1b   = (const float*)d_in[2];
    const float* qkvw  = (const float*)d_in[3];
    const float* qkvb  = (const float*)d_in[4];
    const float* rpb   = (const float*)d_in[5];
    const float* projw = (const float*)d_in[6];
    const float* projb = (const float*)d_in[7];
    const float* n2g   = (const float*)d_in[8];
    const float* n2b   = (const float*)d_in[9];
    const float* fc1w  = (const float*)d_in[10];
    const float* fc1b  = (const float*)d_in[11];
    const float* fc2w  = (const float*)d_in[12];
    const float* fc2b  = (const float*)d_in[13];
    const int*   ridx  = (const int*)  d_in[14];
    float* out = (float*)d_out;

    bf16 *xw, *qkv, *attn, *h2, *wb;
    float *x1, *biasb;
    cudaGetSymbolAddress((void**)&xw,    g_xw);
    cudaGetSymbolAddress((void**)&qkv,   g_qkv);
    cudaGetSymbolAddress((void**)&attn,  g_attn);
    cudaGetSymbolAddress((void**)&x1,    g_x1);
    cudaGetSymbolAddress((void**)&h2,    g_h2);
    cudaGetSymbolAddress((void**)&wb,    g_wb);
    cudaGetSymbolAddress((void**)&biasb, g_bias);

    bf16* qkvw_b  = wb;
    bf16* projw_b = wb + 49152;
    bf16* fc1w_b  = wb + 65536;
    bf16* fc2w_b  = wb + 131072;

    cudaFuncSetAttribute(mlp_fused, cudaFuncAttributeMaxDynamicSharedMemorySize, SMEM_MLP);

    // 0+1) fused: LN1 (+shift/window) AND weight cvt + bias table
    ln_setup<<<LN_BLOCKS + 243, 256>>>(x, n1g, n1b, xw,
                                       qkvw, projw, fc1w, fc2w, wb, rpb, ridx, biasb);

    // 2) QKV projection: [M,128] @ [384,128]^T -> bf16
    bgemm<0><<<dim3(MROWS / BM, 3), 256>>>(xw, qkvw_b, qkvb, nullptr, qkv,
                                           nullptr, nullptr, nullptr,
                                           MROWS, 3 * CDIM, CDIM);

    // 3) tensor-core windowed attention -> bf16
    attn_mma<<<dim3(BATCH * 64, 2), 128>>>(qkv, biasb, attn);

    // 4) proj + window reverse + unshift + residual -> x1 fp32; fused LN2 -> h2 bf16
    bgemm<3><<<dim3(MROWS / BM, 1), 256>>>(attn, projw_b, projb, x, x1,
                                           n2g, n2b, h2,
                                           MROWS, CDIM, CDIM);

    // 5) fused MLP: fc1 + GELU + fc2 + residual -> out fp32
    mlp_fused<<<MROWS / 64, 256, SMEM_MLP>>>(h2, fc1w_b, fc1b, fc2w_b, fc2b, x1, out);
}